// round 1
// baseline (speedup 1.0000x reference)
#include <cuda_runtime.h>
#include <math.h>

// Problem constants (fixed by the dataset problem)
#define BB 4
#define TT 2048
#define CC 1024

// Scratch (allocation-free rule: __device__ globals)
__device__ float g_q[BB * TT * CC];
__device__ float g_k[BB * TT * CC];
__device__ float g_v[BB * TT * CC];
__device__ float g_w[(size_t)BB * TT * TT];   // 64 MB score / prob matrix

// ---------------------------------------------------------------------------
// SGEMM NT:  Cm[m,n] = alpha * sum_k A[m,k] * B[n,k]
// A: [M,K] row-major, B: [N,K] row-major. M,N multiples of 128, K multiple of 16.
// Optional causal tile skip (tiles entirely above the diagonal do no work).
// ---------------------------------------------------------------------------
__global__ __launch_bounds__(256)
void gemm_nt(const float* __restrict__ A, const float* __restrict__ Bm,
             float* __restrict__ Cm, int M, int N, int K, float alpha,
             size_t sA, size_t sB, size_t sC, int causal)
{
    int bz = blockIdx.z;
    A  += (size_t)bz * sA;
    Bm += (size_t)bz * sB;
    Cm += (size_t)bz * sC;

    int rm = blockIdx.y * 128;
    int cn = blockIdx.x * 128;
    if (causal && cn > rm + 127) return;   // fully masked tile

    __shared__ float As[16][132];
    __shared__ float Bs[16][132];

    int tid = threadIdx.x;
    int ty = tid >> 4;          // 0..15
    int tx = tid & 15;          // 0..15
    int lr = tid >> 2;          // 0..63 (loader row)
    int lc = (tid & 3) * 4;     // 0,4,8,12 (loader k-col)

    float acc[8][8];
    #pragma unroll
    for (int i = 0; i < 8; i++)
        #pragma unroll
        for (int j = 0; j < 8; j++) acc[i][j] = 0.f;

    for (int k0 = 0; k0 < K; k0 += 16) {
        #pragma unroll
        for (int p = 0; p < 2; p++) {
            int r = lr + p * 64;
            float4 va = *(const float4*)(A  + (size_t)(rm + r) * K + k0 + lc);
            As[lc + 0][r] = va.x; As[lc + 1][r] = va.y;
            As[lc + 2][r] = va.z; As[lc + 3][r] = va.w;
            float4 vb = *(const float4*)(Bm + (size_t)(cn + r) * K + k0 + lc);
            Bs[lc + 0][r] = vb.x; Bs[lc + 1][r] = vb.y;
            Bs[lc + 2][r] = vb.z; Bs[lc + 3][r] = vb.w;
        }
        __syncthreads();

        #pragma unroll
        for (int kk = 0; kk < 16; kk++) {
            float a[8], b[8];
            #pragma unroll
            for (int i = 0; i < 8; i++) a[i] = As[kk][ty * 8 + i];
            #pragma unroll
            for (int j = 0; j < 8; j++) b[j] = Bs[kk][tx * 8 + j];
            #pragma unroll
            for (int i = 0; i < 8; i++)
                #pragma unroll
                for (int j = 0; j < 8; j++)
                    acc[i][j] = fmaf(a[i], b[j], acc[i][j]);
        }
        __syncthreads();
    }

    #pragma unroll
    for (int i = 0; i < 8; i++) {
        size_t r = (size_t)(rm + ty * 8 + i);
        #pragma unroll
        for (int j = 0; j < 8; j++)
            Cm[r * N + cn + tx * 8 + j] = acc[i][j] * alpha;
    }
}

// ---------------------------------------------------------------------------
// SGEMM NN with causal k-truncation:  Cm[m,n] = sum_{k < min(K, rm+128)} A[m,k]*B[k,n]
// A: [M,K] row-major (probs, zeros above diagonal), B: [K,N] row-major.
// ---------------------------------------------------------------------------
__global__ __launch_bounds__(256)
void gemm_nn_causal(const float* __restrict__ A, const float* __restrict__ Bm,
                    float* __restrict__ Cm, int M, int N, int K,
                    size_t sA, size_t sB, size_t sC)
{
    int bz = blockIdx.z;
    A  += (size_t)bz * sA;
    Bm += (size_t)bz * sB;
    Cm += (size_t)bz * sC;

    int rm = blockIdx.y * 128;
    int cn = blockIdx.x * 128;
    int kmax = min(K, rm + 128);     // probs are zero for s > t

    __shared__ float As[16][132];
    __shared__ float Bs[16][132];

    int tid = threadIdx.x;
    int ty = tid >> 4;
    int tx = tid & 15;
    int lr = tid >> 2;            // A loader
    int lc = (tid & 3) * 4;
    int brow = tid >> 5;          // B loader: 0..7
    int bcol = (tid & 31) * 4;    // 0..124

    float acc[8][8];
    #pragma unroll
    for (int i = 0; i < 8; i++)
        #pragma unroll
        for (int j = 0; j < 8; j++) acc[i][j] = 0.f;

    for (int k0 = 0; k0 < kmax; k0 += 16) {
        #pragma unroll
        for (int p = 0; p < 2; p++) {
            int r = lr + p * 64;
            float4 va = *(const float4*)(A + (size_t)(rm + r) * K + k0 + lc);
            As[lc + 0][r] = va.x; As[lc + 1][r] = va.y;
            As[lc + 2][r] = va.z; As[lc + 3][r] = va.w;
        }
        #pragma unroll
        for (int p = 0; p < 2; p++) {
            int kr = brow + p * 8;
            *(float4*)&Bs[kr][bcol] =
                *(const float4*)(Bm + (size_t)(k0 + kr) * N + cn + bcol);
        }
        __syncthreads();

        #pragma unroll
        for (int kk = 0; kk < 16; kk++) {
            float a[8], b[8];
            #pragma unroll
            for (int i = 0; i < 8; i++) a[i] = As[kk][ty * 8 + i];
            #pragma unroll
            for (int j = 0; j < 8; j++) b[j] = Bs[kk][tx * 8 + j];
            #pragma unroll
            for (int i = 0; i < 8; i++)
                #pragma unroll
                for (int j = 0; j < 8; j++)
                    acc[i][j] = fmaf(a[i], b[j], acc[i][j]);
        }
        __syncthreads();
    }

    #pragma unroll
    for (int i = 0; i < 8; i++) {
        size_t r = (size_t)(rm + ty * 8 + i);
        #pragma unroll
        for (int j = 0; j < 8; j++)
            Cm[r * N + cn + tx * 8 + j] = acc[i][j];
    }
}

// ---------------------------------------------------------------------------
// Row-wise causal softmax over the score matrix (in place).
// One block per (b, t) row. Only entries s <= t are read; s > t written as 0.
// ---------------------------------------------------------------------------
__global__ __launch_bounds__(256)
void softmax_causal(float* __restrict__ Wm)
{
    int row = blockIdx.x;             // 0 .. BB*TT-1
    int b = row / TT, t = row % TT;
    float* p = Wm + (size_t)b * TT * TT + (size_t)t * TT;
    int n = t + 1;
    int tid = threadIdx.x;

    __shared__ float red[256];

    float m = -1e30f;
    for (int i = tid; i < n; i += 256) m = fmaxf(m, p[i]);
    red[tid] = m;
    __syncthreads();
    for (int s = 128; s > 0; s >>= 1) {
        if (tid < s) red[tid] = fmaxf(red[tid], red[tid + s]);
        __syncthreads();
    }
    m = red[0];
    __syncthreads();

    float sum = 0.f;
    for (int i = tid; i < n; i += 256) {
        float e = __expf(p[i] - m);
        p[i] = e;
        sum += e;
    }
    red[tid] = sum;
    __syncthreads();
    for (int s = 128; s > 0; s >>= 1) {
        if (tid < s) red[tid] += red[tid + s];
        __syncthreads();
    }
    float inv = 1.f / red[0];

    for (int i = tid; i < TT; i += 256)
        p[i] = (i < n) ? p[i] * inv : 0.f;
}

// ---------------------------------------------------------------------------
extern "C" void kernel_launch(void* const* d_in, const int* in_sizes, int n_in,
                              void* d_out, int out_size)
{
    const float* x  = (const float*)d_in[0];
    const float* Wk = (const float*)d_in[1];
    const float* Wq = (const float*)d_in[2];
    const float* Wv = (const float*)d_in[3];
    float* out = (float*)d_out;

    float *q, *k, *v, *w;
    cudaGetSymbolAddress((void**)&q, g_q);
    cudaGetSymbolAddress((void**)&k, g_k);
    cudaGetSymbolAddress((void**)&v, g_v);
    cudaGetSymbolAddress((void**)&w, g_w);

    const int M = BB * TT;            // 8192 token rows
    const float scale = 1.0f / 32.0f; // C^-0.5, C=1024

    // 1) QKV projections: y = x @ W^T  (NT GEMM), flattened over (B,T)
    dim3 blk(256);
    dim3 g1(CC / 128, M / 128, 1);
    gemm_nt<<<g1, blk>>>(x, Wk, k, M, CC, CC, 1.0f, 0, 0, 0, 0);
    gemm_nt<<<g1, blk>>>(x, Wq, q, M, CC, CC, 1.0f, 0, 0, 0, 0);
    gemm_nt<<<g1, blk>>>(x, Wv, v, M, CC, CC, 1.0f, 0, 0, 0, 0);

    // 2) scores = scale * q @ k^T per batch, causal tile skip
    dim3 g2(TT / 128, TT / 128, BB);
    gemm_nt<<<g2, blk>>>(q, k, w, TT, TT, CC, scale,
                         (size_t)TT * CC, (size_t)TT * CC, (size_t)TT * TT, 1);

    // 3) causal softmax (in place, zero-fills above diagonal)
    softmax_causal<<<BB * TT, blk>>>(w);

    // 4) out = probs @ v per batch, k-loop truncated at the diagonal
    dim3 g4(CC / 128, TT / 128, BB);
    gemm_nn_causal<<<g4, blk>>>(w, v, out, TT, CC, TT,
                                (size_t)TT * TT, (size_t)TT * CC, (size_t)TT * CC);
}

// round 3
// speedup vs baseline: 1.9501x; 1.9501x over previous
#include <cuda_runtime.h>
#include <cuda_bf16.h>
#include <cstdint>
#include <math.h>

#define BB 4
#define TT 2048
#define CC 1024
#define MT (BB*TT)            /* 8192 flattened token rows */

typedef __nv_bfloat16 nb;

// ---------------- scratch (__device__ globals; no allocs allowed) ----------
__device__ nb    g_xh[MT*CC],  g_xl[MT*CC];
__device__ nb    g_wqh[CC*CC], g_wql[CC*CC];
__device__ nb    g_wkh[CC*CC], g_wkl[CC*CC];
__device__ nb    g_wvh[CC*CC], g_wvl[CC*CC];
__device__ nb    g_qh[MT*CC],  g_ql[MT*CC];
__device__ nb    g_kh[MT*CC],  g_kl[MT*CC];
__device__ float g_v[MT*CC];
__device__ nb    g_vth[(size_t)BB*CC*TT], g_vtl[(size_t)BB*CC*TT];
__device__ float g_w[(size_t)BB*TT*TT];
__device__ nb    g_ph[(size_t)BB*TT*TT], g_pl[(size_t)BB*TT*TT];

// ---------------- helpers ---------------------------------------------------
__device__ __forceinline__ uint32_t smem_u32(const void* p) {
    uint32_t a;
    asm("{ .reg .u64 t; cvta.to.shared.u64 t, %1; cvt.u32.u64 %0, t; }"
        : "=r"(a) : "l"(p));
    return a;
}
__device__ __forceinline__ void cpa16(uint32_t d, const void* s) {
    asm volatile("cp.async.cg.shared.global [%0], [%1], 16;" :: "r"(d), "l"(s));
}
__device__ __forceinline__ void cp_commit() {
    asm volatile("cp.async.commit_group;");
}
__device__ __forceinline__ void ldsm4(uint32_t* r, uint32_t addr) {
    asm volatile("ldmatrix.sync.aligned.m8n8.x4.shared.b16 {%0,%1,%2,%3}, [%4];"
        : "=r"(r[0]), "=r"(r[1]), "=r"(r[2]), "=r"(r[3]) : "r"(addr));
}
__device__ __forceinline__ void mma16816(float* c, const uint32_t* a,
                                         uint32_t b0, uint32_t b1) {
    asm volatile("mma.sync.aligned.m16n8k16.row.col.f32.bf16.bf16.f32 "
        "{%0,%1,%2,%3}, {%4,%5,%6,%7}, {%8,%9}, {%0,%1,%2,%3};"
        : "+f"(c[0]), "+f"(c[1]), "+f"(c[2]), "+f"(c[3])
        : "r"(a[0]), "r"(a[1]), "r"(a[2]), "r"(a[3]), "r"(b0), "r"(b1));
}
__device__ __forceinline__ void split2(float f, nb& h, nb& l) {
    h = __float2bfloat16(f);
    l = __float2bfloat16(f - __bfloat162float(h));
}

// ---------------------------------------------------------------------------
// bf16x3 warp-MMA GEMM (NT): C[m,n] = alpha * sum_k A[m,k]*B[n,k]
// computed as Ah*Bh + Ah*Bl + Al*Bh (fp32 mma.sync accumulate).
// A: [M,K], B: [N,K], bf16 row-major, ld == K. M,N mult of 128, K mult of 32.
// CTA tile 128x128, BK=32, 8 warps (4m x 2n), warp tile 32x64.
// 2-stage cp.async double buffering; pitch-40 padded smem (bank-conflict-free
// for both ldmatrix patterns).
// ---------------------------------------------------------------------------
#define SP 40   /* smem row pitch in elements */

__global__ __launch_bounds__(256, 2)
void gemm3(const nb* __restrict__ Ah, const nb* __restrict__ Al,
           const nb* __restrict__ Bh, const nb* __restrict__ Bl,
           float* __restrict__ Cf, nb* __restrict__ Oh, nb* __restrict__ Ol,
           int N, int K, size_t sA, size_t sB, size_t sC,
           float alpha, int causal, int trunc)
{
    int rm = blockIdx.y * 128;
    int cn = blockIdx.x * 128;
    if (causal && cn > rm + 127) return;     // fully-masked tile

    int bz = blockIdx.z;
    Ah += (size_t)bz * sA;  Al += (size_t)bz * sA;
    Bh += (size_t)bz * sB;  Bl += (size_t)bz * sB;
    if (Cf) Cf += (size_t)bz * sC;
    if (Oh) { Oh += (size_t)bz * sC; Ol += (size_t)bz * sC; }

    int kmax = trunc ? min(K, rm + 128) : K;
    int nch  = kmax >> 5;                    // BK=32 chunks per pass
    int G    = 3 * nch;

    __shared__ __align__(16) nb As[2][128 * SP];
    __shared__ __align__(16) nb Bs[2][128 * SP];

    int tid = threadIdx.x, lane = tid & 31, wid = tid >> 5;
    int wm = wid & 3;          // 0..3  -> 32-row slice
    int wn = wid >> 2;         // 0..1  -> 64-col slice

    uint32_t aS[2] = { smem_u32(As[0]), smem_u32(As[1]) };
    uint32_t bS[2] = { smem_u32(Bs[0]), smem_u32(Bs[1]) };

    // ldmatrix lane offsets (bytes)
    uint32_t aoff = ((uint32_t)(wm * 32 + (lane & 15)) * SP + (lane >> 4) * 8) * 2u;
    uint32_t boff = ((uint32_t)(wn * 64 + ((lane >> 4) & 1) * 8 + (lane & 7)) * SP
                     + ((lane >> 3) & 1) * 8) * 2u;

    // cp.async loader indices: thread covers 2 rows x 16B for A and B each
    int l_row = tid >> 2;          // 0..63  (+64 for second)
    int l_c   = (tid & 3) * 8;     // element col: 0,8,16,24

    float acc[2][8][4];
    #pragma unroll
    for (int mi = 0; mi < 2; mi++)
        #pragma unroll
        for (int ni = 0; ni < 8; ni++)
            #pragma unroll
            for (int j = 0; j < 4; j++) acc[mi][ni][j] = 0.f;

#define LOAD_CHUNK(gg) do {                                                   \
    int _p = (gg) / nch, _c = (gg) - _p * nch, _s = (gg) & 1;                 \
    const nb* _pa = (_p == 2) ? Al : Ah;                                      \
    const nb* _pb = (_p == 1) ? Bl : Bh;                                      \
    size_t _k0 = (size_t)_c * 32;                                             \
    _Pragma("unroll")                                                         \
    for (int _i = 0; _i < 2; _i++) {                                          \
        int _row = l_row + 64 * _i;                                           \
        cpa16(aS[_s] + ((uint32_t)_row * SP + l_c) * 2u,                      \
              _pa + (size_t)(rm + _row) * K + _k0 + l_c);                     \
        cpa16(bS[_s] + ((uint32_t)_row * SP + l_c) * 2u,                      \
              _pb + (size_t)(cn + _row) * K + _k0 + l_c);                     \
    }                                                                         \
    cp_commit();                                                              \
} while (0)

    LOAD_CHUNK(0);

    for (int g = 0; g < G; ++g) {
        if (g + 1 < G) {
            LOAD_CHUNK(g + 1);
            asm volatile("cp.async.wait_group 1;");
        } else {
            asm volatile("cp.async.wait_group 0;");
        }
        __syncthreads();

        int s = g & 1;
        #pragma unroll
        for (int kk = 0; kk < 2; kk++) {
            uint32_t a[2][4];
            #pragma unroll
            for (int mi = 0; mi < 2; mi++)
                ldsm4(a[mi], aS[s] + aoff + mi * (16 * SP * 2) + kk * 32);
            #pragma unroll
            for (int np = 0; np < 4; np++) {
                uint32_t b[4];
                ldsm4(b, bS[s] + boff + np * (16 * SP * 2) + kk * 32);
                #pragma unroll
                for (int mi = 0; mi < 2; mi++) {
                    mma16816(acc[mi][2 * np],     a[mi], b[0], b[1]);
                    mma16816(acc[mi][2 * np + 1], a[mi], b[2], b[3]);
                }
            }
        }
        __syncthreads();
    }
#undef LOAD_CHUNK

    // ---- epilogue ----
    int g4 = lane >> 2, tg = lane & 3;
    #pragma unroll
    for (int mi = 0; mi < 2; mi++) {
        #pragma unroll
        for (int ni = 0; ni < 8; ni++) {
            int r0 = rm + wm * 32 + mi * 16 + g4;
            int cb = cn + wn * 64 + ni * 8 + tg * 2;
            float c0 = acc[mi][ni][0] * alpha, c1 = acc[mi][ni][1] * alpha;
            float c2 = acc[mi][ni][2] * alpha, c3 = acc[mi][ni][3] * alpha;
            if (Cf) {
                *(float2*)(Cf + (size_t)r0 * N + cb)       = make_float2(c0, c1);
                *(float2*)(Cf + (size_t)(r0 + 8) * N + cb) = make_float2(c2, c3);
            } else {
                nb h0, l0, h1, l1;
                split2(c0, h0, l0); split2(c1, h1, l1);
                *(__nv_bfloat162*)(Oh + (size_t)r0 * N + cb) =
                    __nv_bfloat162(h0, h1);
                *(__nv_bfloat162*)(Ol + (size_t)r0 * N + cb) =
                    __nv_bfloat162(l0, l1);
                split2(c2, h0, l0); split2(c3, h1, l1);
                *(__nv_bfloat162*)(Oh + (size_t)(r0 + 8) * N + cb) =
                    __nv_bfloat162(h0, h1);
                *(__nv_bfloat162*)(Ol + (size_t)(r0 + 8) * N + cb) =
                    __nv_bfloat162(l0, l1);
            }
        }
    }
}

// ---------------------------------------------------------------------------
// elementwise fp32 -> (hi, lo) bf16 split
// ---------------------------------------------------------------------------
__global__ __launch_bounds__(256)
void split_elem(const float* __restrict__ in, nb* __restrict__ h,
                nb* __restrict__ l, int n)
{
    int i = blockIdx.x * 256 + threadIdx.x;
    if (i < n) {
        float f = in[i];
        nb a, b; split2(f, a, b);
        h[i] = a; l[i] = b;
    }
}

// ---------------------------------------------------------------------------
// V [B,T,C] fp32 -> V^T [B,C,T] bf16 hi/lo (K-major for the PV NT GEMM)
// ---------------------------------------------------------------------------
__global__ __launch_bounds__(256)
void tsplit_v(const float* __restrict__ v, nb* __restrict__ oh, nb* __restrict__ ol)
{
    __shared__ float t[32][33];
    int b = blockIdx.z;
    const float* vb = v + (size_t)b * TT * CC;
    nb* ohb = oh + (size_t)b * CC * TT;
    nb* olb = ol + (size_t)b * CC * TT;
    int c0 = blockIdx.x * 32, t0 = blockIdx.y * 32;
    int tx = threadIdx.x, ty = threadIdx.y;          // (32, 8)

    #pragma unroll
    for (int i = 0; i < 4; i++)
        t[ty + i * 8][tx] = vb[(size_t)(t0 + ty + i * 8) * CC + c0 + tx];
    __syncthreads();
    #pragma unroll
    for (int i = 0; i < 4; i++) {
        float f = t[tx][ty + i * 8];                 // = v[t0+tx][c0+ty+8i]
        size_t o = (size_t)(c0 + ty + i * 8) * TT + t0 + tx;
        nb h, l; split2(f, h, l);
        ohb[o] = h; olb[o] = l;
    }
}

// ---------------------------------------------------------------------------
// causal softmax over raw scores w (fp32), emitting bf16 hi/lo prob splits
// ---------------------------------------------------------------------------
__global__ __launch_bounds__(256)
void softmax_split(float* __restrict__ w, nb* __restrict__ ph, nb* __restrict__ pl)
{
    int row = blockIdx.x;
    int b = row >> 11, t = row & 2047;
    float* p  = w  + ((size_t)b * TT + t) * TT;
    nb*   hh  = ph + ((size_t)b * TT + t) * TT;
    nb*   ll  = pl + ((size_t)b * TT + t) * TT;
    int n = t + 1;
    int tid = threadIdx.x;

    __shared__ float red[256];

    float m = -1e30f;
    for (int i = tid; i < n; i += 256) m = fmaxf(m, p[i]);
    red[tid] = m; __syncthreads();
    for (int s = 128; s > 0; s >>= 1) {
        if (tid < s) red[tid] = fmaxf(red[tid], red[tid + s]);
        __syncthreads();
    }
    m = red[0]; __syncthreads();

    float sum = 0.f;
    for (int i = tid; i < n; i += 256) {
        float e = __expf(p[i] - m);
        p[i] = e;
        sum += e;
    }
    red[tid] = sum; __syncthreads();
    for (int s = 128; s > 0; s >>= 1) {
        if (tid < s) red[tid] += red[tid + s];
        __syncthreads();
    }
    float inv = 1.f / red[0];

    for (int i = tid; i < TT; i += 256) {
        if (i < n) {
            nb h, l; split2(p[i] * inv, h, l);
            hh[i] = h; ll[i] = l;
        } else {
            hh[i] = __float2bfloat16(0.f);
            ll[i] = __float2bfloat16(0.f);
        }
    }
}

// ---------------------------------------------------------------------------
extern "C" void kernel_launch(void* const* d_in, const int* in_sizes, int n_in,
                              void* d_out, int out_size)
{
    const float* x  = (const float*)d_in[0];
    const float* Wk = (const float*)d_in[1];
    const float* Wq = (const float*)d_in[2];
    const float* Wv = (const float*)d_in[3];
    float* out = (float*)d_out;

    nb *xh, *xl, *wqh, *wql, *wkh, *wkl, *wvh, *wvl;
    nb *qh, *ql, *kh, *kl, *vth, *vtl, *ph, *pl;
    float *v, *w;
    cudaGetSymbolAddress((void**)&xh, g_xh);   cudaGetSymbolAddress((void**)&xl, g_xl);
    cudaGetSymbolAddress((void**)&wqh, g_wqh); cudaGetSymbolAddress((void**)&wql, g_wql);
    cudaGetSymbolAddress((void**)&wkh, g_wkh); cudaGetSymbolAddress((void**)&wkl, g_wkl);
    cudaGetSymbolAddress((void**)&wvh, g_wvh); cudaGetSymbolAddress((void**)&wvl, g_wvl);
    cudaGetSymbolAddress((void**)&qh, g_qh);   cudaGetSymbolAddress((void**)&ql, g_ql);
    cudaGetSymbolAddress((void**)&kh, g_kh);   cudaGetSymbolAddress((void**)&kl, g_kl);
    cudaGetSymbolAddress((void**)&v, g_v);
    cudaGetSymbolAddress((void**)&vth, g_vth); cudaGetSymbolAddress((void**)&vtl, g_vtl);
    cudaGetSymbolAddress((void**)&w, g_w);
    cudaGetSymbolAddress((void**)&ph, g_ph);   cudaGetSymbolAddress((void**)&pl, g_pl);

    const float scale = 1.0f / 32.0f;   // C^-0.5

    // 1) split inputs
    split_elem<<<(MT * CC + 255) / 256, 256>>>(x,  xh,  xl,  MT * CC);
    split_elem<<<(CC * CC + 255) / 256, 256>>>(Wq, wqh, wql, CC * CC);
    split_elem<<<(CC * CC + 255) / 256, 256>>>(Wk, wkh, wkl, CC * CC);
    split_elem<<<(CC * CC + 255) / 256, 256>>>(Wv, wvh, wvl, CC * CC);

    // 2) projections  y = x @ W^T   (q,k emit splits; v emits fp32)
    dim3 gp(CC / 128, MT / 128, 1);
    gemm3<<<gp, 256>>>(xh, xl, wqh, wql, nullptr, qh, ql,
                       CC, CC, 0, 0, 0, 1.0f, 0, 0);
    gemm3<<<gp, 256>>>(xh, xl, wkh, wkl, nullptr, kh, kl,
                       CC, CC, 0, 0, 0, 1.0f, 0, 0);
    gemm3<<<gp, 256>>>(xh, xl, wvh, wvl, v, nullptr, nullptr,
                       CC, CC, 0, 0, 0, 1.0f, 0, 0);

    // 3) transpose-split V -> V^T (bf16 hi/lo)
    tsplit_v<<<dim3(CC / 32, TT / 32, BB), dim3(32, 8)>>>(v, vth, vtl);

    // 4) scores = scale * q @ k^T   (causal tile skip, fp32 out)
    dim3 gs(TT / 128, TT / 128, BB);
    gemm3<<<gs, 256>>>(qh, ql, kh, kl, w, nullptr, nullptr,
                       TT, CC, (size_t)TT * CC, (size_t)TT * CC,
                       (size_t)TT * TT, scale, 1, 0);

    // 5) softmax -> prob splits
    softmax_split<<<BB * TT, 256>>>(w, ph, pl);

    // 6) out = P @ V   (k-loop truncated at the diagonal)
    dim3 go(CC / 128, TT / 128, BB);
    gemm3<<<go, 256>>>(ph, pl, vth, vtl, out, nullptr, nullptr,
                       CC, TT, (size_t)TT * TT, (size_t)CC * TT,
                       (size_t)TT * CC, 1.0f, 0, 1);
}

// round 4
// speedup vs baseline: 3.9773x; 2.0395x over previous
#include <cuda_runtime.h>
#include <cuda_fp16.h>
#include <cstdint>
#include <math.h>

#define BB 4
#define TT 2048
#define CC 1024
#define MT (BB*TT)            /* 8192 flattened token rows */

typedef __half hf;

// ---------------- scratch (__device__ globals; no allocs allowed) ----------
__device__ hf    g_xh[MT*CC],  g_xl[MT*CC];
__device__ hf    g_wq[CC*CC],  g_wk[CC*CC],  g_wv[CC*CC];
__device__ hf    g_qh[MT*CC],  g_ql[MT*CC];
__device__ hf    g_kh[MT*CC];
__device__ float g_v[MT*CC];
__device__ hf    g_vt[(size_t)BB*CC*TT];
__device__ float g_w[(size_t)BB*TT*TT];
__device__ hf    g_ph[(size_t)BB*TT*TT], g_pl[(size_t)BB*TT*TT];

// ---------------- helpers ---------------------------------------------------
__device__ __forceinline__ uint32_t smem_u32(const void* p) {
    uint32_t a;
    asm("{ .reg .u64 t; cvta.to.shared.u64 t, %1; cvt.u32.u64 %0, t; }"
        : "=r"(a) : "l"(p));
    return a;
}
__device__ __forceinline__ void cpa16(uint32_t d, const void* s) {
    asm volatile("cp.async.cg.shared.global [%0], [%1], 16;" :: "r"(d), "l"(s));
}
__device__ __forceinline__ void cp_commit() {
    asm volatile("cp.async.commit_group;");
}
__device__ __forceinline__ void ldsm4(uint32_t* r, uint32_t addr) {
    asm volatile("ldmatrix.sync.aligned.m8n8.x4.shared.b16 {%0,%1,%2,%3}, [%4];"
        : "=r"(r[0]), "=r"(r[1]), "=r"(r[2]), "=r"(r[3]) : "r"(addr));
}
__device__ __forceinline__ void mma16816(float* c, const uint32_t* a,
                                         uint32_t b0, uint32_t b1) {
    asm volatile("mma.sync.aligned.m16n8k16.row.col.f32.f16.f16.f32 "
        "{%0,%1,%2,%3}, {%4,%5,%6,%7}, {%8,%9}, {%0,%1,%2,%3};"
        : "+f"(c[0]), "+f"(c[1]), "+f"(c[2]), "+f"(c[3])
        : "r"(a[0]), "r"(a[1]), "r"(a[2]), "r"(a[3]), "r"(b0), "r"(b1));
}
__device__ __forceinline__ void split2(float f, hf& h, hf& l) {
    h = __float2half_rn(f);
    l = __float2half_rn(f - __half2float(h));
}

// ---------------------------------------------------------------------------
// fp16x2 warp-MMA GEMM core (NT): acc += (Ah+Al)[m,:] . Bh[n,:]
// A hi/lo + B hi, row-major, ld == K.  CTA tile 128x128, BK=64, 8 warps
// (4m x 2n, warp tile 32x64). 2-stage cp.async pipeline; B tile shared by
// both A-passes. Pitch-72 smem rows (conflict-free ldmatrix).
// ---------------------------------------------------------------------------
#define SP 72                      /* smem row pitch, elements */
#define TB (128 * SP * 2)          /* bytes per 128x64 tile buffer */
#define GSMEM (6 * TB)             /* 110592 B: {Ah,Al,B} x 2 stages */

__device__ __forceinline__ void gemm_core(
    const hf* __restrict__ Ah, const hf* __restrict__ Al,
    const hf* __restrict__ Bh, int K, int rm, int cn, int kmax,
    char* smem, float acc[2][8][4])
{
    uint32_t sb = smem_u32(smem);
    uint32_t aH[2] = { sb,          sb + TB };
    uint32_t aL[2] = { sb + 2*TB,   sb + 3*TB };
    uint32_t bS[2] = { sb + 4*TB,   sb + 5*TB };

    int tid = threadIdx.x, lane = tid & 31, wid = tid >> 5;
    int wm = wid & 3, wn = wid >> 2;

    int l_row = tid >> 3;          // 0..31
    int l_c   = (tid & 7) * 8;     // element col 0..56 (16B chunks)

    uint32_t aoff = ((uint32_t)(wm * 32 + (lane & 15)) * SP + (lane >> 4) * 8) * 2u;
    uint32_t boff = ((uint32_t)(wn * 64 + ((lane >> 4) & 1) * 8 + (lane & 7)) * SP
                     + ((lane >> 3) & 1) * 8) * 2u;

    int nch = kmax >> 6;

#define LOADC(cc) do {                                                        \
    int _s = (cc) & 1; size_t _k0 = (size_t)(cc) * 64;                        \
    _Pragma("unroll")                                                         \
    for (int _i = 0; _i < 4; _i++) {                                          \
        int _r = l_row + 32 * _i;                                             \
        uint32_t _so = ((uint32_t)_r * SP + l_c) * 2u;                        \
        cpa16(aH[_s] + _so, Ah + (size_t)(rm + _r) * K + _k0 + l_c);          \
        cpa16(aL[_s] + _so, Al + (size_t)(rm + _r) * K + _k0 + l_c);          \
        cpa16(bS[_s] + _so, Bh + (size_t)(cn + _r) * K + _k0 + l_c);          \
    }                                                                         \
    cp_commit();                                                              \
} while (0)

    LOADC(0);

    for (int c = 0; c < nch; c++) {
        if (c + 1 < nch) {
            LOADC(c + 1);
            asm volatile("cp.async.wait_group 1;");
        } else {
            asm volatile("cp.async.wait_group 0;");
        }
        __syncthreads();

        int s = c & 1;
        #pragma unroll
        for (int kk = 0; kk < 4; kk++) {
            uint32_t ah[2][4], al[2][4];
            #pragma unroll
            for (int mi = 0; mi < 2; mi++) {
                ldsm4(ah[mi], aH[s] + aoff + mi * (16 * SP * 2) + kk * 32);
                ldsm4(al[mi], aL[s] + aoff + mi * (16 * SP * 2) + kk * 32);
            }
            #pragma unroll
            for (int np = 0; np < 4; np++) {
                uint32_t b[4];
                ldsm4(b, bS[s] + boff + np * (16 * SP * 2) + kk * 32);
                #pragma unroll
                for (int mi = 0; mi < 2; mi++) {
                    mma16816(acc[mi][2 * np],     ah[mi], b[0], b[1]);
                    mma16816(acc[mi][2 * np + 1], ah[mi], b[2], b[3]);
                    mma16816(acc[mi][2 * np],     al[mi], b[0], b[1]);
                    mma16816(acc[mi][2 * np + 1], al[mi], b[2], b[3]);
                }
            }
        }
        __syncthreads();
    }
#undef LOADC
}

#define EPI_IDX()                                                             \
    int lane = threadIdx.x & 31, wid = threadIdx.x >> 5;                      \
    int wm = wid & 3, wn = wid >> 2;                                          \
    int g4 = lane >> 2, tg = lane & 3;

// ---------------------------------------------------------------------------
// Fused QKV projection: z=0 -> qh,ql ; z=1 -> kh ; z=2 -> v (fp32)
// ---------------------------------------------------------------------------
__global__ __launch_bounds__(256, 2)
void proj_kernel(const hf* __restrict__ xh, const hf* __restrict__ xl,
                 const hf* __restrict__ wq, const hf* __restrict__ wk,
                 const hf* __restrict__ wv,
                 hf* __restrict__ qh, hf* __restrict__ ql,
                 hf* __restrict__ kh, float* __restrict__ v)
{
    extern __shared__ char smem[];
    int rm = blockIdx.y * 128, cn = blockIdx.x * 128, z = blockIdx.z;
    const hf* B = (z == 0) ? wq : (z == 1) ? wk : wv;

    float acc[2][8][4];
    #pragma unroll
    for (int a = 0; a < 2; a++)
        #pragma unroll
        for (int b = 0; b < 8; b++)
            #pragma unroll
            for (int c = 0; c < 4; c++) acc[a][b][c] = 0.f;

    gemm_core(xh, xl, B, CC, rm, cn, CC, smem, acc);

    EPI_IDX();
    #pragma unroll
    for (int mi = 0; mi < 2; mi++)
        #pragma unroll
        for (int ni = 0; ni < 8; ni++) {
            int r0 = rm + wm * 32 + mi * 16 + g4;
            int cb = cn + wn * 64 + ni * 8 + tg * 2;
            float c0 = acc[mi][ni][0], c1 = acc[mi][ni][1];
            float c2 = acc[mi][ni][2], c3 = acc[mi][ni][3];
            if (z == 2) {
                *(float2*)(v + (size_t)r0 * CC + cb)       = make_float2(c0, c1);
                *(float2*)(v + (size_t)(r0 + 8) * CC + cb) = make_float2(c2, c3);
            } else if (z == 1) {
                *(__half2*)(kh + (size_t)r0 * CC + cb) =
                    __halves2half2(__float2half_rn(c0), __float2half_rn(c1));
                *(__half2*)(kh + (size_t)(r0 + 8) * CC + cb) =
                    __halves2half2(__float2half_rn(c2), __float2half_rn(c3));
            } else {
                hf h0, l0, h1, l1;
                split2(c0, h0, l0); split2(c1, h1, l1);
                *(__half2*)(qh + (size_t)r0 * CC + cb) = __halves2half2(h0, h1);
                *(__half2*)(ql + (size_t)r0 * CC + cb) = __halves2half2(l0, l1);
                split2(c2, h0, l0); split2(c3, h1, l1);
                *(__half2*)(qh + (size_t)(r0 + 8) * CC + cb) = __halves2half2(h0, h1);
                *(__half2*)(ql + (size_t)(r0 + 8) * CC + cb) = __halves2half2(l0, l1);
            }
        }
}

// ---------------------------------------------------------------------------
// scores = scale * q @ k^T  — triangular tile launch (lower tiles only)
// ---------------------------------------------------------------------------
__global__ __launch_bounds__(256, 2)
void score_kernel(const hf* __restrict__ qh, const hf* __restrict__ ql,
                  const hf* __restrict__ kh, float* __restrict__ w, float scale)
{
    extern __shared__ char smem[];
    int ti = blockIdx.x;                          // 0..135
    int i = (int)((sqrtf(8.f * ti + 1.f) - 1.f) * 0.5f);
    while ((i + 1) * (i + 2) / 2 <= ti) i++;
    while (i * (i + 1) / 2 > ti) i--;
    int j = ti - i * (i + 1) / 2;
    int rm = i * 128, cn = j * 128;

    int bz = blockIdx.z;
    qh += (size_t)bz * TT * CC;  ql += (size_t)bz * TT * CC;
    kh += (size_t)bz * TT * CC;  w  += (size_t)bz * TT * TT;

    float acc[2][8][4];
    #pragma unroll
    for (int a = 0; a < 2; a++)
        #pragma unroll
        for (int b = 0; b < 8; b++)
            #pragma unroll
            for (int c = 0; c < 4; c++) acc[a][b][c] = 0.f;

    gemm_core(qh, ql, kh, CC, rm, cn, CC, smem, acc);

    EPI_IDX();
    #pragma unroll
    for (int mi = 0; mi < 2; mi++)
        #pragma unroll
        for (int ni = 0; ni < 8; ni++) {
            int r0 = rm + wm * 32 + mi * 16 + g4;
            int cb = cn + wn * 64 + ni * 8 + tg * 2;
            *(float2*)(w + (size_t)r0 * TT + cb) =
                make_float2(acc[mi][ni][0] * scale, acc[mi][ni][1] * scale);
            *(float2*)(w + (size_t)(r0 + 8) * TT + cb) =
                make_float2(acc[mi][ni][2] * scale, acc[mi][ni][3] * scale);
        }
}

// ---------------------------------------------------------------------------
// out = P @ V  (vT is [C][T] K-major; k-loop truncated at diagonal)
// ---------------------------------------------------------------------------
__global__ __launch_bounds__(256, 2)
void pv_kernel(const hf* __restrict__ ph, const hf* __restrict__ pl,
               const hf* __restrict__ vt, float* __restrict__ out)
{
    extern __shared__ char smem[];
    int iy = gridDim.y - 1 - blockIdx.y;          // heavy tiles first
    int rm = iy * 128, cn = blockIdx.x * 128;
    int kmax = rm + 128;

    int bz = blockIdx.z;
    ph += (size_t)bz * TT * TT;  pl += (size_t)bz * TT * TT;
    vt += (size_t)bz * CC * TT;  out += (size_t)bz * TT * CC;

    float acc[2][8][4];
    #pragma unroll
    for (int a = 0; a < 2; a++)
        #pragma unroll
        for (int b = 0; b < 8; b++)
            #pragma unroll
            for (int c = 0; c < 4; c++) acc[a][b][c] = 0.f;

    gemm_core(ph, pl, vt, TT, rm, cn, kmax, smem, acc);

    EPI_IDX();
    #pragma unroll
    for (int mi = 0; mi < 2; mi++)
        #pragma unroll
        for (int ni = 0; ni < 8; ni++) {
            int r0 = rm + wm * 32 + mi * 16 + g4;
            int cb = cn + wn * 64 + ni * 8 + tg * 2;
            *(float2*)(out + (size_t)r0 * CC + cb) =
                make_float2(acc[mi][ni][0], acc[mi][ni][1]);
            *(float2*)(out + (size_t)(r0 + 8) * CC + cb) =
                make_float2(acc[mi][ni][2], acc[mi][ni][3]);
        }
}

// ---------------------------------------------------------------------------
// elementwise fp32 -> (hi, lo) fp16 split / hi-only convert
// ---------------------------------------------------------------------------
__global__ __launch_bounds__(256)
void split_elem(const float* __restrict__ in, hf* __restrict__ h,
                hf* __restrict__ l, int n)
{
    int i = blockIdx.x * 256 + threadIdx.x;
    if (i < n) {
        hf a, b; split2(in[i], a, b);
        h[i] = a; l[i] = b;
    }
}
__global__ __launch_bounds__(256)
void conv_h(const float* __restrict__ in, hf* __restrict__ h, int n)
{
    int i = blockIdx.x * 256 + threadIdx.x;
    if (i < n) h[i] = __float2half_rn(in[i]);
}

// ---------------------------------------------------------------------------
// V [B,T,C] fp32 -> V^T [B,C,T] fp16 (K-major for the PV NT GEMM)
// ---------------------------------------------------------------------------
__global__ __launch_bounds__(256)
void tsplit_v(const float* __restrict__ v, hf* __restrict__ oh)
{
    __shared__ float t[32][33];
    int b = blockIdx.z;
    const float* vb = v + (size_t)b * TT * CC;
    hf* ohb = oh + (size_t)b * CC * TT;
    int c0 = blockIdx.x * 32, t0 = blockIdx.y * 32;
    int tx = threadIdx.x, ty = threadIdx.y;          // (32, 8)

    #pragma unroll
    for (int i = 0; i < 4; i++)
        t[ty + i * 8][tx] = vb[(size_t)(t0 + ty + i * 8) * CC + c0 + tx];
    __syncthreads();
    #pragma unroll
    for (int i = 0; i < 4; i++) {
        float f = t[tx][ty + i * 8];                 // = v[t0+tx][c0+ty+8i]
        ohb[(size_t)(c0 + ty + i * 8) * TT + t0 + tx] = __float2half_rn(f);
    }
}

// ---------------------------------------------------------------------------
// causal softmax over raw scores w (fp32), emitting fp16 hi/lo prob splits
// ---------------------------------------------------------------------------
__global__ __launch_bounds__(256)
void softmax_split(float* __restrict__ w, hf* __restrict__ ph, hf* __restrict__ pl)
{
    int row = blockIdx.x;
    int b = row >> 11, t = row & 2047;
    float* p  = w  + ((size_t)b * TT + t) * TT;
    hf*   hh  = ph + ((size_t)b * TT + t) * TT;
    hf*   ll  = pl + ((size_t)b * TT + t) * TT;
    int n = t + 1;
    int tid = threadIdx.x;

    __shared__ float red[256];

    float m = -1e30f;
    for (int i = tid; i < n; i += 256) m = fmaxf(m, p[i]);
    red[tid] = m; __syncthreads();
    for (int s = 128; s > 0; s >>= 1) {
        if (tid < s) red[tid] = fmaxf(red[tid], red[tid + s]);
        __syncthreads();
    }
    m = red[0]; __syncthreads();

    float sum = 0.f;
    for (int i = tid; i < n; i += 256) {
        float e = __expf(p[i] - m);
        p[i] = e;
        sum += e;
    }
    red[tid] = sum; __syncthreads();
    for (int s = 128; s > 0; s >>= 1) {
        if (tid < s) red[tid] += red[tid + s];
        __syncthreads();
    }
    float inv = 1.f / red[0];

    for (int i = tid; i < TT; i += 256) {
        if (i < n) {
            hf h, l; split2(p[i] * inv, h, l);
            hh[i] = h; ll[i] = l;
        } else {
            hh[i] = __float2half_rn(0.f);
            ll[i] = __float2half_rn(0.f);
        }
    }
}

// ---------------------------------------------------------------------------
extern "C" void kernel_launch(void* const* d_in, const int* in_sizes, int n_in,
                              void* d_out, int out_size)
{
    const float* x  = (const float*)d_in[0];
    const float* Wk = (const float*)d_in[1];
    const float* Wq = (const float*)d_in[2];
    const float* Wv = (const float*)d_in[3];
    float* out = (float*)d_out;

    hf *xh, *xl, *wq, *wk, *wv, *qh, *ql, *kh, *vt, *ph, *pl;
    float *v, *w;
    cudaGetSymbolAddress((void**)&xh, g_xh); cudaGetSymbolAddress((void**)&xl, g_xl);
    cudaGetSymbolAddress((void**)&wq, g_wq); cudaGetSymbolAddress((void**)&wk, g_wk);
    cudaGetSymbolAddress((void**)&wv, g_wv);
    cudaGetSymbolAddress((void**)&qh, g_qh); cudaGetSymbolAddress((void**)&ql, g_ql);
    cudaGetSymbolAddress((void**)&kh, g_kh);
    cudaGetSymbolAddress((void**)&v, g_v);   cudaGetSymbolAddress((void**)&vt, g_vt);
    cudaGetSymbolAddress((void**)&w, g_w);
    cudaGetSymbolAddress((void**)&ph, g_ph); cudaGetSymbolAddress((void**)&pl, g_pl);

    cudaFuncSetAttribute(proj_kernel,  cudaFuncAttributeMaxDynamicSharedMemorySize, GSMEM);
    cudaFuncSetAttribute(score_kernel, cudaFuncAttributeMaxDynamicSharedMemorySize, GSMEM);
    cudaFuncSetAttribute(pv_kernel,    cudaFuncAttributeMaxDynamicSharedMemorySize, GSMEM);

    const float scale = 1.0f / 32.0f;   // C^-0.5

    // 1) input conversions
    split_elem<<<(MT * CC + 255) / 256, 256>>>(x, xh, xl, MT * CC);
    conv_h<<<(CC * CC + 255) / 256, 256>>>(Wq, wq, CC * CC);
    conv_h<<<(CC * CC + 255) / 256, 256>>>(Wk, wk, CC * CC);
    conv_h<<<(CC * CC + 255) / 256, 256>>>(Wv, wv, CC * CC);

    // 2) fused QKV projection (z selects weight + epilogue)
    proj_kernel<<<dim3(CC / 128, MT / 128, 3), 256, GSMEM>>>(
        xh, xl, wq, wk, wv, qh, ql, kh, v);

    // 3) V -> V^T fp16
    tsplit_v<<<dim3(CC / 32, TT / 32, BB), dim3(32, 8)>>>(v, vt);

    // 4) scores (triangular tile set)
    score_kernel<<<dim3(136, 1, BB), 256, GSMEM>>>(qh, ql, kh, w, scale);

    // 5) softmax -> fp16 prob splits
    softmax_split<<<BB * TT, 256>>>(w, ph, pl);

    // 6) out = P @ V
    pv_kernel<<<dim3(CC / 128, TT / 128, BB), 256, GSMEM>>>(ph, pl, vt, out);
}

// round 5
// speedup vs baseline: 4.5198x; 1.1364x over previous
#include <cuda_runtime.h>
#include <cuda_fp16.h>
#include <cstdint>
#include <math.h>

#define BB 4
#define TT 2048
#define CC 1024
#define MT (BB*TT)            /* 8192 flattened token rows */

typedef __half hf;

// ---------------- scratch (__device__ globals; no allocs allowed) ----------
__device__ hf    g_xh[MT*CC],  g_xl[MT*CC];
__device__ hf    g_wq[CC*CC],  g_wk[CC*CC],  g_wv[CC*CC];
__device__ hf    g_qh[MT*CC],  g_ql[MT*CC];
__device__ hf    g_kh[MT*CC];
__device__ hf    g_v[MT*CC];
__device__ hf    g_vt[(size_t)BB*CC*TT];
__device__ float g_w[(size_t)BB*TT*TT];
__device__ hf    g_ph[(size_t)BB*TT*TT];

// ---------------- helpers ---------------------------------------------------
__device__ __forceinline__ uint32_t smem_u32(const void* p) {
    uint32_t a;
    asm("{ .reg .u64 t; cvta.to.shared.u64 t, %1; cvt.u32.u64 %0, t; }"
        : "=r"(a) : "l"(p));
    return a;
}
__device__ __forceinline__ void cpa16(uint32_t d, const void* s) {
    asm volatile("cp.async.cg.shared.global [%0], [%1], 16;" :: "r"(d), "l"(s));
}
__device__ __forceinline__ void cp_commit() {
    asm volatile("cp.async.commit_group;");
}
__device__ __forceinline__ void ldsm4(uint32_t* r, uint32_t addr) {
    asm volatile("ldmatrix.sync.aligned.m8n8.x4.shared.b16 {%0,%1,%2,%3}, [%4];"
        : "=r"(r[0]), "=r"(r[1]), "=r"(r[2]), "=r"(r[3]) : "r"(addr));
}
__device__ __forceinline__ void mma16816(float* c, const uint32_t* a,
                                         uint32_t b0, uint32_t b1) {
    asm volatile("mma.sync.aligned.m16n8k16.row.col.f32.f16.f16.f32 "
        "{%0,%1,%2,%3}, {%4,%5,%6,%7}, {%8,%9}, {%0,%1,%2,%3};"
        : "+f"(c[0]), "+f"(c[1]), "+f"(c[2]), "+f"(c[3])
        : "r"(a[0]), "r"(a[1]), "r"(a[2]), "r"(a[3]), "r"(b0), "r"(b1));
}
__device__ __forceinline__ void split2(float f, hf& h, hf& l) {
    h = __float2half_rn(f);
    l = __float2half_rn(f - __half2float(h));
}

// ---------------------------------------------------------------------------
// fp16 warp-MMA GEMM core (NT). LO=true: acc += (Ah+Al).Bh (2 passes, shared
// B frags). LO=false: acc += Ah.Bh.  Row-major, ld == K.  CTA tile 128x128,
// BK=64, 8 warps (4m x 2n, warp tile 32x64), 2-stage cp.async.
// smem layout: [Ah0 Ah1 B0 B1 (Al0 Al1)] so the LO=false path is compact.
// ---------------------------------------------------------------------------
#define SP 72                      /* smem row pitch, elements */
#define TB (128 * SP * 2)          /* bytes per 128x64 tile buffer */
#define GSMEM (6 * TB)             /* LO path: {Ah,B,Al} x 2 stages */
#define PSM   (4 * TB)             /* no-lo path: {Ah,B} x 2 stages */

template <bool LO>
__device__ __forceinline__ void gemm_core(
    const hf* __restrict__ Ah, const hf* __restrict__ Al,
    const hf* __restrict__ Bh, int K, int rm, int cn, int kmax,
    char* smem, float acc[2][8][4])
{
    uint32_t sb = smem_u32(smem);
    uint32_t aH[2] = { sb,          sb + TB };
    uint32_t bS[2] = { sb + 2*TB,   sb + 3*TB };
    uint32_t aL[2] = { sb + 4*TB,   sb + 5*TB };

    int tid = threadIdx.x, lane = tid & 31, wid = tid >> 5;
    int wm = wid & 3, wn = wid >> 2;

    int l_row = tid >> 3;          // 0..31
    int l_c   = (tid & 7) * 8;     // element col 0..56 (16B chunks)

    uint32_t aoff = ((uint32_t)(wm * 32 + (lane & 15)) * SP + (lane >> 4) * 8) * 2u;
    uint32_t boff = ((uint32_t)(wn * 64 + ((lane >> 4) & 1) * 8 + (lane & 7)) * SP
                     + ((lane >> 3) & 1) * 8) * 2u;

    int nch = kmax >> 6;

#define LOADC(cc) do {                                                        \
    int _s = (cc) & 1; size_t _k0 = (size_t)(cc) * 64;                        \
    _Pragma("unroll")                                                         \
    for (int _i = 0; _i < 4; _i++) {                                          \
        int _r = l_row + 32 * _i;                                             \
        uint32_t _so = ((uint32_t)_r * SP + l_c) * 2u;                        \
        cpa16(aH[_s] + _so, Ah + (size_t)(rm + _r) * K + _k0 + l_c);          \
        if (LO) cpa16(aL[_s] + _so, Al + (size_t)(rm + _r) * K + _k0 + l_c);  \
        cpa16(bS[_s] + _so, Bh + (size_t)(cn + _r) * K + _k0 + l_c);          \
    }                                                                         \
    cp_commit();                                                              \
} while (0)

    LOADC(0);

    for (int c = 0; c < nch; c++) {
        if (c + 1 < nch) {
            LOADC(c + 1);
            asm volatile("cp.async.wait_group 1;");
        } else {
            asm volatile("cp.async.wait_group 0;");
        }
        __syncthreads();

        int s = c & 1;
        #pragma unroll
        for (int kk = 0; kk < 4; kk++) {
            uint32_t ah[2][4], al[2][4];
            #pragma unroll
            for (int mi = 0; mi < 2; mi++) {
                ldsm4(ah[mi], aH[s] + aoff + mi * (16 * SP * 2) + kk * 32);
                if (LO) ldsm4(al[mi], aL[s] + aoff + mi * (16 * SP * 2) + kk * 32);
            }
            #pragma unroll
            for (int np = 0; np < 4; np++) {
                uint32_t b[4];
                ldsm4(b, bS[s] + boff + np * (16 * SP * 2) + kk * 32);
                #pragma unroll
                for (int mi = 0; mi < 2; mi++) {
                    mma16816(acc[mi][2 * np],     ah[mi], b[0], b[1]);
                    mma16816(acc[mi][2 * np + 1], ah[mi], b[2], b[3]);
                    if (LO) {
                        mma16816(acc[mi][2 * np],     al[mi], b[0], b[1]);
                        mma16816(acc[mi][2 * np + 1], al[mi], b[2], b[3]);
                    }
                }
            }
        }
        __syncthreads();
    }
#undef LOADC
}

#define EPI_IDX()                                                             \
    int lane = threadIdx.x & 31, wid = threadIdx.x >> 5;                      \
    int wm = wid & 3, wn = wid >> 2;                                          \
    int g4 = lane >> 2, tg = lane & 3;

#define ZERO_ACC(acc)                                                         \
    _Pragma("unroll")                                                         \
    for (int _a = 0; _a < 2; _a++)                                            \
        _Pragma("unroll")                                                     \
        for (int _b = 0; _b < 8; _b++)                                        \
            _Pragma("unroll")                                                 \
            for (int _c = 0; _c < 4; _c++) (acc)[_a][_b][_c] = 0.f;

// ---------------------------------------------------------------------------
// Fused QKV projection: z=0 -> qh,ql ; z=1 -> kh ; z=2 -> v (fp16)
// ---------------------------------------------------------------------------
__global__ __launch_bounds__(256, 2)
void proj_kernel(const hf* __restrict__ xh, const hf* __restrict__ xl,
                 const hf* __restrict__ wq, const hf* __restrict__ wk,
                 const hf* __restrict__ wv,
                 hf* __restrict__ qh, hf* __restrict__ ql,
                 hf* __restrict__ kh, hf* __restrict__ v)
{
    extern __shared__ char smem[];
    int rm = blockIdx.y * 128, cn = blockIdx.x * 128, z = blockIdx.z;
    const hf* B = (z == 0) ? wq : (z == 1) ? wk : wv;

    float acc[2][8][4];
    ZERO_ACC(acc);
    gemm_core<true>(xh, xl, B, CC, rm, cn, CC, smem, acc);

    EPI_IDX();
    #pragma unroll
    for (int mi = 0; mi < 2; mi++)
        #pragma unroll
        for (int ni = 0; ni < 8; ni++) {
            int r0 = rm + wm * 32 + mi * 16 + g4;
            int cb = cn + wn * 64 + ni * 8 + tg * 2;
            float c0 = acc[mi][ni][0], c1 = acc[mi][ni][1];
            float c2 = acc[mi][ni][2], c3 = acc[mi][ni][3];
            if (z == 0) {
                hf h0, l0, h1, l1;
                split2(c0, h0, l0); split2(c1, h1, l1);
                *(__half2*)(qh + (size_t)r0 * CC + cb) = __halves2half2(h0, h1);
                *(__half2*)(ql + (size_t)r0 * CC + cb) = __halves2half2(l0, l1);
                split2(c2, h0, l0); split2(c3, h1, l1);
                *(__half2*)(qh + (size_t)(r0 + 8) * CC + cb) = __halves2half2(h0, h1);
                *(__half2*)(ql + (size_t)(r0 + 8) * CC + cb) = __halves2half2(l0, l1);
            } else {
                hf* dst = (z == 1) ? kh : v;
                *(__half2*)(dst + (size_t)r0 * CC + cb) =
                    __halves2half2(__float2half_rn(c0), __float2half_rn(c1));
                *(__half2*)(dst + (size_t)(r0 + 8) * CC + cb) =
                    __halves2half2(__float2half_rn(c2), __float2half_rn(c3));
            }
        }
}

// ---------------------------------------------------------------------------
// scores = scale * q @ k^T  — triangular tile launch (lower tiles only)
// ---------------------------------------------------------------------------
__global__ __launch_bounds__(256, 2)
void score_kernel(const hf* __restrict__ qh, const hf* __restrict__ ql,
                  const hf* __restrict__ kh, float* __restrict__ w, float scale)
{
    extern __shared__ char smem[];
    int ti = blockIdx.x;                          // 0..135
    int i = (int)((sqrtf(8.f * ti + 1.f) - 1.f) * 0.5f);
    while ((i + 1) * (i + 2) / 2 <= ti) i++;
    while (i * (i + 1) / 2 > ti) i--;
    int j = ti - i * (i + 1) / 2;
    int rm = i * 128, cn = j * 128;

    int bz = blockIdx.z;
    qh += (size_t)bz * TT * CC;  ql += (size_t)bz * TT * CC;
    kh += (size_t)bz * TT * CC;  w  += (size_t)bz * TT * TT;

    float acc[2][8][4];
    ZERO_ACC(acc);
    gemm_core<true>(qh, ql, kh, CC, rm, cn, CC, smem, acc);

    EPI_IDX();
    #pragma unroll
    for (int mi = 0; mi < 2; mi++)
        #pragma unroll
        for (int ni = 0; ni < 8; ni++) {
            int r0 = rm + wm * 32 + mi * 16 + g4;
            int cb = cn + wn * 64 + ni * 8 + tg * 2;
            *(float2*)(w + (size_t)r0 * TT + cb) =
                make_float2(acc[mi][ni][0] * scale, acc[mi][ni][1] * scale);
            *(float2*)(w + (size_t)(r0 + 8) * TT + cb) =
                make_float2(acc[mi][ni][2] * scale, acc[mi][ni][3] * scale);
        }
}

// ---------------------------------------------------------------------------
// out = P @ V  — single-pass P-hi (P positive, well-conditioned).
// vT is [C][T] K-major; k-loop truncated at the diagonal.
// ---------------------------------------------------------------------------
__global__ __launch_bounds__(256, 2)
void pv_kernel(const hf* __restrict__ ph, const hf* __restrict__ vt,
               float* __restrict__ out)
{
    extern __shared__ char smem[];
    int iy = gridDim.y - 1 - blockIdx.y;          // heavy tiles first
    int rm = iy * 128, cn = blockIdx.x * 128;
    int kmax = rm + 128;

    int bz = blockIdx.z;
    ph += (size_t)bz * TT * TT;
    vt += (size_t)bz * CC * TT;  out += (size_t)bz * TT * CC;

    float acc[2][8][4];
    ZERO_ACC(acc);
    gemm_core<false>(ph, nullptr, vt, TT, rm, cn, kmax, smem, acc);

    EPI_IDX();
    #pragma unroll
    for (int mi = 0; mi < 2; mi++)
        #pragma unroll
        for (int ni = 0; ni < 8; ni++) {
            int r0 = rm + wm * 32 + mi * 16 + g4;
            int cb = cn + wn * 64 + ni * 8 + tg * 2;
            *(float2*)(out + (size_t)r0 * CC + cb) =
                make_float2(acc[mi][ni][0], acc[mi][ni][1]);
            *(float2*)(out + (size_t)(r0 + 8) * CC + cb) =
                make_float2(acc[mi][ni][2], acc[mi][ni][3]);
        }
}

// ---------------------------------------------------------------------------
// input conversions
// ---------------------------------------------------------------------------
__global__ __launch_bounds__(256)
void split_elem(const float* __restrict__ in, hf* __restrict__ h,
                hf* __restrict__ l, int n)
{
    int i = blockIdx.x * 256 + threadIdx.x;
    if (i < n) {
        hf a, b; split2(in[i], a, b);
        h[i] = a; l[i] = b;
    }
}
__global__ __launch_bounds__(256)
void conv3(const float* __restrict__ a, const float* __restrict__ b,
           const float* __restrict__ c, hf* __restrict__ oa,
           hf* __restrict__ ob, hf* __restrict__ oc, int n)
{
    int z = blockIdx.y;
    const float* in = (z == 0) ? a : (z == 1) ? b : c;
    hf* o = (z == 0) ? oa : (z == 1) ? ob : oc;
    int i = blockIdx.x * 256 + threadIdx.x;
    if (i < n) o[i] = __float2half_rn(in[i]);
}

// ---------------------------------------------------------------------------
// V [B,T,C] fp16 -> V^T [B,C,T] fp16 (K-major for the PV NT GEMM)
// ---------------------------------------------------------------------------
__global__ __launch_bounds__(256)
void tsplit_v(const hf* __restrict__ v, hf* __restrict__ oh)
{
    __shared__ float t[32][33];
    int b = blockIdx.z;
    const hf* vb = v + (size_t)b * TT * CC;
    hf* ohb = oh + (size_t)b * CC * TT;
    int c0 = blockIdx.x * 32, t0 = blockIdx.y * 32;
    int tx = threadIdx.x, ty = threadIdx.y;          // (32, 8)

    #pragma unroll
    for (int i = 0; i < 4; i++)
        t[ty + i * 8][tx] = __half2float(vb[(size_t)(t0 + ty + i * 8) * CC + c0 + tx]);
    __syncthreads();
    #pragma unroll
    for (int i = 0; i < 4; i++) {
        float f = t[tx][ty + i * 8];                 // = v[t0+tx][c0+ty+8i]
        ohb[(size_t)(c0 + ty + i * 8) * TT + t0 + tx] = __float2half_rn(f);
    }
}

// ---------------------------------------------------------------------------
// causal softmax over raw scores w (fp32) -> fp16 probs (hi only).
// exp recomputed in pass 3 so w is never written back.
// ---------------------------------------------------------------------------
__global__ __launch_bounds__(256)
void softmax_h(const float* __restrict__ w, hf* __restrict__ ph)
{
    int row = blockIdx.x;
    int b = row >> 11, t = row & 2047;
    const float* p = w  + ((size_t)b * TT + t) * TT;
    hf*          o = ph + ((size_t)b * TT + t) * TT;
    int n = t + 1;
    int tid = threadIdx.x;

    __shared__ float red[256];

    float m = -1e30f;
    for (int i = tid; i < n; i += 256) m = fmaxf(m, p[i]);
    red[tid] = m; __syncthreads();
    for (int s = 128; s > 0; s >>= 1) {
        if (tid < s) red[tid] = fmaxf(red[tid], red[tid + s]);
        __syncthreads();
    }
    m = red[0]; __syncthreads();

    float sum = 0.f;
    for (int i = tid; i < n; i += 256) sum += __expf(p[i] - m);
    red[tid] = sum; __syncthreads();
    for (int s = 128; s > 0; s >>= 1) {
        if (tid < s) red[tid] += red[tid + s];
        __syncthreads();
    }
    float inv = 1.f / red[0];

    for (int i = tid * 2; i < TT; i += 512) {
        float e0 = (i     < n) ? __expf(p[i]     - m) * inv : 0.f;
        float e1 = (i + 1 < n) ? __expf(p[i + 1] - m) * inv : 0.f;
        *(__half2*)(o + i) =
            __halves2half2(__float2half_rn(e0), __float2half_rn(e1));
    }
}

// ---------------------------------------------------------------------------
extern "C" void kernel_launch(void* const* d_in, const int* in_sizes, int n_in,
                              void* d_out, int out_size)
{
    const float* x  = (const float*)d_in[0];
    const float* Wk = (const float*)d_in[1];
    const float* Wq = (const float*)d_in[2];
    const float* Wv = (const float*)d_in[3];
    float* out = (float*)d_out;

    hf *xh, *xl, *wq, *wk, *wv, *qh, *ql, *kh, *v, *vt, *ph;
    float *w;
    cudaGetSymbolAddress((void**)&xh, g_xh); cudaGetSymbolAddress((void**)&xl, g_xl);
    cudaGetSymbolAddress((void**)&wq, g_wq); cudaGetSymbolAddress((void**)&wk, g_wk);
    cudaGetSymbolAddress((void**)&wv, g_wv);
    cudaGetSymbolAddress((void**)&qh, g_qh); cudaGetSymbolAddress((void**)&ql, g_ql);
    cudaGetSymbolAddress((void**)&kh, g_kh);
    cudaGetSymbolAddress((void**)&v, g_v);   cudaGetSymbolAddress((void**)&vt, g_vt);
    cudaGetSymbolAddress((void**)&w, g_w);
    cudaGetSymbolAddress((void**)&ph, g_ph);

    cudaFuncSetAttribute(proj_kernel,  cudaFuncAttributeMaxDynamicSharedMemorySize, GSMEM);
    cudaFuncSetAttribute(score_kernel, cudaFuncAttributeMaxDynamicSharedMemorySize, GSMEM);
    cudaFuncSetAttribute(pv_kernel,    cudaFuncAttributeMaxDynamicSharedMemorySize, PSM);

    const float scale = 1.0f / 32.0f;   // C^-0.5

    // 1) input conversions
    split_elem<<<(MT * CC + 255) / 256, 256>>>(x, xh, xl, MT * CC);
    conv3<<<dim3((CC * CC + 255) / 256, 3), 256>>>(Wq, Wk, Wv, wq, wk, wv, CC * CC);

    // 2) fused QKV projection (z selects weight + epilogue)
    proj_kernel<<<dim3(CC / 128, MT / 128, 3), 256, GSMEM>>>(
        xh, xl, wq, wk, wv, qh, ql, kh, v);

    // 3) V -> V^T fp16
    tsplit_v<<<dim3(CC / 32, TT / 32, BB), dim3(32, 8)>>>(v, vt);

    // 4) scores (triangular tile set)
    score_kernel<<<dim3(136, 1, BB), 256, GSMEM>>>(qh, ql, kh, w, scale);

    // 5) softmax -> fp16 probs
    softmax_h<<<BB * TT, 256>>>(w, ph);

    // 6) out = P @ V (single-pass)
    pv_kernel<<<dim3(CC / 128, TT / 128, BB), 256, PSM>>>(ph, vt, out);
}

// round 6
// speedup vs baseline: 5.7306x; 1.2679x over previous
#include <cuda_runtime.h>
#include <cuda_fp16.h>
#include <cstdint>
#include <math.h>

#define BB 4
#define TT 2048
#define CC 1024
#define MT (BB*TT)            /* 8192 flattened token rows */

typedef __half hf;

// ---------------- scratch (__device__ globals; no allocs allowed) ----------
__device__ hf    g_xh[MT*CC];
__device__ hf    g_wq[CC*CC],  g_wk[CC*CC],  g_wv[CC*CC];
__device__ hf    g_qh[MT*CC],  g_ql[MT*CC];
__device__ hf    g_kh[MT*CC];
__device__ hf    g_v[MT*CC];
__device__ hf    g_vt[(size_t)BB*CC*TT];
__device__ float g_w[(size_t)BB*TT*TT];
__device__ hf    g_ph[(size_t)BB*TT*TT];

// ---------------- helpers ---------------------------------------------------
__device__ __forceinline__ uint32_t smem_u32(const void* p) {
    uint32_t a;
    asm("{ .reg .u64 t; cvta.to.shared.u64 t, %1; cvt.u32.u64 %0, t; }"
        : "=r"(a) : "l"(p));
    return a;
}
__device__ __forceinline__ void cpa16(uint32_t d, const void* s) {
    asm volatile("cp.async.cg.shared.global [%0], [%1], 16;" :: "r"(d), "l"(s));
}
__device__ __forceinline__ void cp_commit() {
    asm volatile("cp.async.commit_group;");
}
__device__ __forceinline__ void ldsm4(uint32_t* r, uint32_t addr) {
    asm volatile("ldmatrix.sync.aligned.m8n8.x4.shared.b16 {%0,%1,%2,%3}, [%4];"
        : "=r"(r[0]), "=r"(r[1]), "=r"(r[2]), "=r"(r[3]) : "r"(addr));
}
__device__ __forceinline__ void mma16816(float* c, const uint32_t* a,
                                         uint32_t b0, uint32_t b1) {
    asm volatile("mma.sync.aligned.m16n8k16.row.col.f32.f16.f16.f32 "
        "{%0,%1,%2,%3}, {%4,%5,%6,%7}, {%8,%9}, {%0,%1,%2,%3};"
        : "+f"(c[0]), "+f"(c[1]), "+f"(c[2]), "+f"(c[3])
        : "r"(a[0]), "r"(a[1]), "r"(a[2]), "r"(a[3]), "r"(b0), "r"(b1));
}
__device__ __forceinline__ void split2(float f, hf& h, hf& l) {
    h = __float2half_rn(f);
    l = __float2half_rn(f - __half2float(h));
}

// ---------------------------------------------------------------------------
// fp16 warp-MMA GEMM core (NT). LO=true: acc += (Ah+Al).Bh (2 passes, shared
// B frags). LO=false: acc += Ah.Bh.  Row-major, ld == K.  CTA tile 128x128,
// BK=64, 8 warps (4m x 2n, warp tile 32x64), 2-stage cp.async.
// smem layout: [Ah0 Ah1 B0 B1 (Al0 Al1)] so the LO=false path is compact.
// ---------------------------------------------------------------------------
#define SP 72                      /* smem row pitch, elements */
#define TB (128 * SP * 2)          /* bytes per 128x64 tile buffer */
#define GSMEM (6 * TB)             /* LO path: {Ah,B,Al} x 2 stages */
#define PSM   (4 * TB)             /* no-lo path: {Ah,B} x 2 stages */

template <bool LO>
__device__ __forceinline__ void gemm_core(
    const hf* __restrict__ Ah, const hf* __restrict__ Al,
    const hf* __restrict__ Bh, int K, int rm, int cn, int kmax,
    char* smem, float acc[2][8][4])
{
    uint32_t sb = smem_u32(smem);
    uint32_t aH[2] = { sb,          sb + TB };
    uint32_t bS[2] = { sb + 2*TB,   sb + 3*TB };
    uint32_t aL[2] = { sb + 4*TB,   sb + 5*TB };

    int tid = threadIdx.x, lane = tid & 31, wid = tid >> 5;
    int wm = wid & 3, wn = wid >> 2;

    int l_row = tid >> 3;          // 0..31
    int l_c   = (tid & 7) * 8;     // element col 0..56 (16B chunks)

    uint32_t aoff = ((uint32_t)(wm * 32 + (lane & 15)) * SP + (lane >> 4) * 8) * 2u;
    uint32_t boff = ((uint32_t)(wn * 64 + ((lane >> 4) & 1) * 8 + (lane & 7)) * SP
                     + ((lane >> 3) & 1) * 8) * 2u;

    int nch = kmax >> 6;

#define LOADC(cc) do {                                                        \
    int _s = (cc) & 1; size_t _k0 = (size_t)(cc) * 64;                        \
    _Pragma("unroll")                                                         \
    for (int _i = 0; _i < 4; _i++) {                                          \
        int _r = l_row + 32 * _i;                                             \
        uint32_t _so = ((uint32_t)_r * SP + l_c) * 2u;                        \
        cpa16(aH[_s] + _so, Ah + (size_t)(rm + _r) * K + _k0 + l_c);          \
        if (LO) cpa16(aL[_s] + _so, Al + (size_t)(rm + _r) * K + _k0 + l_c);  \
        cpa16(bS[_s] + _so, Bh + (size_t)(cn + _r) * K + _k0 + l_c);          \
    }                                                                         \
    cp_commit();                                                              \
} while (0)

    LOADC(0);

    for (int c = 0; c < nch; c++) {
        if (c + 1 < nch) {
            LOADC(c + 1);
            asm volatile("cp.async.wait_group 1;");
        } else {
            asm volatile("cp.async.wait_group 0;");
        }
        __syncthreads();

        int s = c & 1;
        #pragma unroll
        for (int kk = 0; kk < 4; kk++) {
            uint32_t ah[2][4], al[2][4];
            #pragma unroll
            for (int mi = 0; mi < 2; mi++) {
                ldsm4(ah[mi], aH[s] + aoff + mi * (16 * SP * 2) + kk * 32);
                if (LO) ldsm4(al[mi], aL[s] + aoff + mi * (16 * SP * 2) + kk * 32);
            }
            #pragma unroll
            for (int np = 0; np < 4; np++) {
                uint32_t b[4];
                ldsm4(b, bS[s] + boff + np * (16 * SP * 2) + kk * 32);
                #pragma unroll
                for (int mi = 0; mi < 2; mi++) {
                    mma16816(acc[mi][2 * np],     ah[mi], b[0], b[1]);
                    mma16816(acc[mi][2 * np + 1], ah[mi], b[2], b[3]);
                    if (LO) {
                        mma16816(acc[mi][2 * np],     al[mi], b[0], b[1]);
                        mma16816(acc[mi][2 * np + 1], al[mi], b[2], b[3]);
                    }
                }
            }
        }
        __syncthreads();
    }
#undef LOADC
}

#define EPI_IDX()                                                             \
    int lane = threadIdx.x & 31, wid = threadIdx.x >> 5;                      \
    int wm = wid & 3, wn = wid >> 2;                                          \
    int g4 = lane >> 2, tg = lane & 3;

#define ZERO_ACC(acc)                                                         \
    _Pragma("unroll")                                                         \
    for (int _a = 0; _a < 2; _a++)                                            \
        _Pragma("unroll")                                                     \
        for (int _b = 0; _b < 8; _b++)                                        \
            _Pragma("unroll")                                                 \
            for (int _c = 0; _c < 4; _c++) (acc)[_a][_b][_c] = 0.f;

// ---------------------------------------------------------------------------
// Fused QKV projection (single-pass fp16): z=0 -> qh,ql ; z=1 -> kh ; z=2 -> v
// q keeps an fp16 hi/lo split (score GEMM A-side stays 2-pass accurate).
// ---------------------------------------------------------------------------
__global__ __launch_bounds__(256, 2)
void proj_kernel(const hf* __restrict__ xh,
                 const hf* __restrict__ wq, const hf* __restrict__ wk,
                 const hf* __restrict__ wv,
                 hf* __restrict__ qh, hf* __restrict__ ql,
                 hf* __restrict__ kh, hf* __restrict__ v)
{
    extern __shared__ char smem[];
    int rm = blockIdx.y * 128, cn = blockIdx.x * 128, z = blockIdx.z;
    const hf* B = (z == 0) ? wq : (z == 1) ? wk : wv;

    float acc[2][8][4];
    ZERO_ACC(acc);
    gemm_core<false>(xh, nullptr, B, CC, rm, cn, CC, smem, acc);

    EPI_IDX();
    #pragma unroll
    for (int mi = 0; mi < 2; mi++)
        #pragma unroll
        for (int ni = 0; ni < 8; ni++) {
            int r0 = rm + wm * 32 + mi * 16 + g4;
            int cb = cn + wn * 64 + ni * 8 + tg * 2;
            float c0 = acc[mi][ni][0], c1 = acc[mi][ni][1];
            float c2 = acc[mi][ni][2], c3 = acc[mi][ni][3];
            if (z == 0) {
                hf h0, l0, h1, l1;
                split2(c0, h0, l0); split2(c1, h1, l1);
                *(__half2*)(qh + (size_t)r0 * CC + cb) = __halves2half2(h0, h1);
                *(__half2*)(ql + (size_t)r0 * CC + cb) = __halves2half2(l0, l1);
                split2(c2, h0, l0); split2(c3, h1, l1);
                *(__half2*)(qh + (size_t)(r0 + 8) * CC + cb) = __halves2half2(h0, h1);
                *(__half2*)(ql + (size_t)(r0 + 8) * CC + cb) = __halves2half2(l0, l1);
            } else {
                hf* dst = (z == 1) ? kh : v;
                *(__half2*)(dst + (size_t)r0 * CC + cb) =
                    __halves2half2(__float2half_rn(c0), __float2half_rn(c1));
                *(__half2*)(dst + (size_t)(r0 + 8) * CC + cb) =
                    __halves2half2(__float2half_rn(c2), __float2half_rn(c3));
            }
        }
}

// ---------------------------------------------------------------------------
// scores = scale * q @ k^T  — triangular tile launch (lower tiles only)
// ---------------------------------------------------------------------------
__global__ __launch_bounds__(256, 2)
void score_kernel(const hf* __restrict__ qh, const hf* __restrict__ ql,
                  const hf* __restrict__ kh, float* __restrict__ w, float scale)
{
    extern __shared__ char smem[];
    int ti = blockIdx.x;                          // 0..135
    int i = (int)((sqrtf(8.f * ti + 1.f) - 1.f) * 0.5f);
    while ((i + 1) * (i + 2) / 2 <= ti) i++;
    while (i * (i + 1) / 2 > ti) i--;
    int j = ti - i * (i + 1) / 2;
    int rm = i * 128, cn = j * 128;

    int bz = blockIdx.z;
    qh += (size_t)bz * TT * CC;  ql += (size_t)bz * TT * CC;
    kh += (size_t)bz * TT * CC;  w  += (size_t)bz * TT * TT;

    float acc[2][8][4];
    ZERO_ACC(acc);
    gemm_core<true>(qh, ql, kh, CC, rm, cn, CC, smem, acc);

    EPI_IDX();
    #pragma unroll
    for (int mi = 0; mi < 2; mi++)
        #pragma unroll
        for (int ni = 0; ni < 8; ni++) {
            int r0 = rm + wm * 32 + mi * 16 + g4;
            int cb = cn + wn * 64 + ni * 8 + tg * 2;
            *(float2*)(w + (size_t)r0 * TT + cb) =
                make_float2(acc[mi][ni][0] * scale, acc[mi][ni][1] * scale);
            *(float2*)(w + (size_t)(r0 + 8) * TT + cb) =
                make_float2(acc[mi][ni][2] * scale, acc[mi][ni][3] * scale);
        }
}

// ---------------------------------------------------------------------------
// out = P @ V  — single-pass P-hi (P positive, well-conditioned).
// vT is [C][T] K-major; k-loop truncated at the diagonal.
// ---------------------------------------------------------------------------
__global__ __launch_bounds__(256, 2)
void pv_kernel(const hf* __restrict__ ph, const hf* __restrict__ vt,
               float* __restrict__ out)
{
    extern __shared__ char smem[];
    int iy = gridDim.y - 1 - blockIdx.y;          // heavy tiles first
    int rm = iy * 128, cn = blockIdx.x * 128;
    int kmax = rm + 128;

    int bz = blockIdx.z;
    ph += (size_t)bz * TT * TT;
    vt += (size_t)bz * CC * TT;  out += (size_t)bz * TT * CC;

    float acc[2][8][4];
    ZERO_ACC(acc);
    gemm_core<false>(ph, nullptr, vt, TT, rm, cn, kmax, smem, acc);

    EPI_IDX();
    #pragma unroll
    for (int mi = 0; mi < 2; mi++)
        #pragma unroll
        for (int ni = 0; ni < 8; ni++) {
            int r0 = rm + wm * 32 + mi * 16 + g4;
            int cb = cn + wn * 64 + ni * 8 + tg * 2;
            *(float2*)(out + (size_t)r0 * CC + cb) =
                make_float2(acc[mi][ni][0], acc[mi][ni][1]);
            *(float2*)(out + (size_t)(r0 + 8) * CC + cb) =
                make_float2(acc[mi][ni][2], acc[mi][ni][3]);
        }
}

// ---------------------------------------------------------------------------
// input conversions (fp32 -> fp16, rounded)
// ---------------------------------------------------------------------------
__global__ __launch_bounds__(256)
void conv_h(const float* __restrict__ in, hf* __restrict__ h, int n)
{
    int i = blockIdx.x * 256 + threadIdx.x;
    if (i < n) h[i] = __float2half_rn(in[i]);
}
__global__ __launch_bounds__(256)
void conv3(const float* __restrict__ a, const float* __restrict__ b,
           const float* __restrict__ c, hf* __restrict__ oa,
           hf* __restrict__ ob, hf* __restrict__ oc, int n)
{
    int z = blockIdx.y;
    const float* in = (z == 0) ? a : (z == 1) ? b : c;
    hf* o = (z == 0) ? oa : (z == 1) ? ob : oc;
    int i = blockIdx.x * 256 + threadIdx.x;
    if (i < n) o[i] = __float2half_rn(in[i]);
}

// ---------------------------------------------------------------------------
// V [B,T,C] fp16 -> V^T [B,C,T] fp16 (K-major for the PV NT GEMM)
// ---------------------------------------------------------------------------
__global__ __launch_bounds__(256)
void tsplit_v(const hf* __restrict__ v, hf* __restrict__ oh)
{
    __shared__ float t[32][33];
    int b = blockIdx.z;
    const hf* vb = v + (size_t)b * TT * CC;
    hf* ohb = oh + (size_t)b * CC * TT;
    int c0 = blockIdx.x * 32, t0 = blockIdx.y * 32;
    int tx = threadIdx.x, ty = threadIdx.y;          // (32, 8)

    #pragma unroll
    for (int i = 0; i < 4; i++)
        t[ty + i * 8][tx] = __half2float(vb[(size_t)(t0 + ty + i * 8) * CC + c0 + tx]);
    __syncthreads();
    #pragma unroll
    for (int i = 0; i < 4; i++) {
        float f = t[tx][ty + i * 8];                 // = v[t0+tx][c0+ty+8i]
        ohb[(size_t)(c0 + ty + i * 8) * TT + t0 + tx] = __float2half_rn(f);
    }
}

// ---------------------------------------------------------------------------
// causal softmax over raw scores w (fp32) -> fp16 probs (hi only).
// exp recomputed in pass 3 so w is never written back.
// ---------------------------------------------------------------------------
__global__ __launch_bounds__(256)
void softmax_h(const float* __restrict__ w, hf* __restrict__ ph)
{
    int row = blockIdx.x;
    int b = row >> 11, t = row & 2047;
    const float* p = w  + ((size_t)b * TT + t) * TT;
    hf*          o = ph + ((size_t)b * TT + t) * TT;
    int n = t + 1;
    int tid = threadIdx.x;

    __shared__ float red[256];

    float m = -1e30f;
    for (int i = tid; i < n; i += 256) m = fmaxf(m, p[i]);
    red[tid] = m; __syncthreads();
    for (int s = 128; s > 0; s >>= 1) {
        if (tid < s) red[tid] = fmaxf(red[tid], red[tid + s]);
        __syncthreads();
    }
    m = red[0]; __syncthreads();

    float sum = 0.f;
    for (int i = tid; i < n; i += 256) sum += __expf(p[i] - m);
    red[tid] = sum; __syncthreads();
    for (int s = 128; s > 0; s >>= 1) {
        if (tid < s) red[tid] += red[tid + s];
        __syncthreads();
    }
    float inv = 1.f / red[0];

    for (int i = tid * 2; i < TT; i += 512) {
        float e0 = (i     < n) ? __expf(p[i]     - m) * inv : 0.f;
        float e1 = (i + 1 < n) ? __expf(p[i + 1] - m) * inv : 0.f;
        *(__half2*)(o + i) =
            __halves2half2(__float2half_rn(e0), __float2half_rn(e1));
    }
}

// ---------------------------------------------------------------------------
extern "C" void kernel_launch(void* const* d_in, const int* in_sizes, int n_in,
                              void* d_out, int out_size)
{
    const float* x  = (const float*)d_in[0];
    const float* Wk = (const float*)d_in[1];
    const float* Wq = (const float*)d_in[2];
    const float* Wv = (const float*)d_in[3];
    float* out = (float*)d_out;

    hf *xh, *wq, *wk, *wv, *qh, *ql, *kh, *v, *vt, *ph;
    float *w;
    cudaGetSymbolAddress((void**)&xh, g_xh);
    cudaGetSymbolAddress((void**)&wq, g_wq); cudaGetSymbolAddress((void**)&wk, g_wk);
    cudaGetSymbolAddress((void**)&wv, g_wv);
    cudaGetSymbolAddress((void**)&qh, g_qh); cudaGetSymbolAddress((void**)&ql, g_ql);
    cudaGetSymbolAddress((void**)&kh, g_kh);
    cudaGetSymbolAddress((void**)&v, g_v);   cudaGetSymbolAddress((void**)&vt, g_vt);
    cudaGetSymbolAddress((void**)&w, g_w);
    cudaGetSymbolAddress((void**)&ph, g_ph);

    cudaFuncSetAttribute(proj_kernel,  cudaFuncAttributeMaxDynamicSharedMemorySize, PSM);
    cudaFuncSetAttribute(score_kernel, cudaFuncAttributeMaxDynamicSharedMemorySize, GSMEM);
    cudaFuncSetAttribute(pv_kernel,    cudaFuncAttributeMaxDynamicSharedMemorySize, PSM);

    const float scale = 1.0f / 32.0f;   // C^-0.5

    // 1) input conversions (all fp16 hi)
    conv_h<<<(MT * CC + 255) / 256, 256>>>(x, xh, MT * CC);
    conv3<<<dim3((CC * CC + 255) / 256, 3), 256>>>(Wq, Wk, Wv, wq, wk, wv, CC * CC);

    // 2) fused QKV projection, single-pass fp16 (z selects weight + epilogue)
    proj_kernel<<<dim3(CC / 128, MT / 128, 3), 256, PSM>>>(
        xh, wq, wk, wv, qh, ql, kh, v);

    // 3) V -> V^T fp16
    tsplit_v<<<dim3(CC / 32, TT / 32, BB), dim3(32, 8)>>>(v, vt);

    // 4) scores (triangular tile set, q 2-pass)
    score_kernel<<<dim3(136, 1, BB), 256, GSMEM>>>(qh, ql, kh, w, scale);

    // 5) softmax -> fp16 probs
    softmax_h<<<BB * TT, 256>>>(w, ph);

    // 6) out = P @ V (single-pass)
    pv_kernel<<<dim3(CC / 128, TT / 128, BB), 256, PSM>>>(ph, vt, out);
}

// round 7
// speedup vs baseline: 6.4131x; 1.1191x over previous
#include <cuda_runtime.h>
#include <cuda_fp16.h>
#include <cstdint>
#include <math.h>

#define BB 4
#define TT 2048
#define CC 1024
#define MT (BB*TT)            /* 8192 flattened token rows */

typedef __half hf;

// ---------------- scratch (__device__ globals; no allocs allowed) ----------
__device__ hf    g_xh[MT*CC];
__device__ hf    g_wq[CC*CC],  g_wk[CC*CC],  g_wv[CC*CC];
__device__ hf    g_qh[MT*CC];
__device__ hf    g_kh[MT*CC];
__device__ hf    g_v[MT*CC];
__device__ hf    g_vt[(size_t)BB*CC*TT];
__device__ float g_w[(size_t)BB*TT*TT];
__device__ hf    g_ph[(size_t)BB*TT*TT];

// ---------------- helpers ---------------------------------------------------
__device__ __forceinline__ uint32_t smem_u32(const void* p) {
    uint32_t a;
    asm("{ .reg .u64 t; cvta.to.shared.u64 t, %1; cvt.u32.u64 %0, t; }"
        : "=r"(a) : "l"(p));
    return a;
}
__device__ __forceinline__ void cpa16(uint32_t d, const void* s) {
    asm volatile("cp.async.cg.shared.global [%0], [%1], 16;" :: "r"(d), "l"(s));
}
__device__ __forceinline__ void cp_commit() {
    asm volatile("cp.async.commit_group;");
}
__device__ __forceinline__ void ldsm4(uint32_t* r, uint32_t addr) {
    asm volatile("ldmatrix.sync.aligned.m8n8.x4.shared.b16 {%0,%1,%2,%3}, [%4];"
        : "=r"(r[0]), "=r"(r[1]), "=r"(r[2]), "=r"(r[3]) : "r"(addr));
}
__device__ __forceinline__ void mma16816(float* c, const uint32_t* a,
                                         uint32_t b0, uint32_t b1) {
    asm volatile("mma.sync.aligned.m16n8k16.row.col.f32.f16.f16.f32 "
        "{%0,%1,%2,%3}, {%4,%5,%6,%7}, {%8,%9}, {%0,%1,%2,%3};"
        : "+f"(c[0]), "+f"(c[1]), "+f"(c[2]), "+f"(c[3])
        : "r"(a[0]), "r"(a[1]), "r"(a[2]), "r"(a[3]), "r"(b0), "r"(b1));
}

// ---------------------------------------------------------------------------
// fp16 warp-MMA GEMM core (NT): acc += Ah . Bh, both [*,K] row-major, ld==K.
// CTA tile 128x128, BK=64, 8 warps (4m x 2n, warp tile 32x64),
// 2-stage cp.async. Pitch-72 smem rows (conflict-free ldmatrix).
// ---------------------------------------------------------------------------
#define SP 72                      /* smem row pitch, elements */
#define TB (128 * SP * 2)          /* bytes per 128x64 tile buffer */
#define PSM (4 * TB)               /* {A,B} x 2 stages = 73728 B */

__device__ __forceinline__ void gemm_core(
    const hf* __restrict__ Ah, const hf* __restrict__ Bh,
    int K, int rm, int cn, int kmax, char* smem, float acc[2][8][4])
{
    uint32_t sb = smem_u32(smem);
    uint32_t aH[2] = { sb,          sb + TB };
    uint32_t bS[2] = { sb + 2*TB,   sb + 3*TB };

    int tid = threadIdx.x, lane = tid & 31, wid = tid >> 5;
    int wm = wid & 3, wn = wid >> 2;

    int l_row = tid >> 3;          // 0..31
    int l_c   = (tid & 7) * 8;     // element col 0..56 (16B chunks)

    uint32_t aoff = ((uint32_t)(wm * 32 + (lane & 15)) * SP + (lane >> 4) * 8) * 2u;
    uint32_t boff = ((uint32_t)(wn * 64 + ((lane >> 4) & 1) * 8 + (lane & 7)) * SP
                     + ((lane >> 3) & 1) * 8) * 2u;

    int nch = kmax >> 6;

#define LOADC(cc) do {                                                        \
    int _s = (cc) & 1; size_t _k0 = (size_t)(cc) * 64;                        \
    _Pragma("unroll")                                                         \
    for (int _i = 0; _i < 4; _i++) {                                          \
        int _r = l_row + 32 * _i;                                             \
        uint32_t _so = ((uint32_t)_r * SP + l_c) * 2u;                        \
        cpa16(aH[_s] + _so, Ah + (size_t)(rm + _r) * K + _k0 + l_c);          \
        cpa16(bS[_s] + _so, Bh + (size_t)(cn + _r) * K + _k0 + l_c);          \
    }                                                                         \
    cp_commit();                                                              \
} while (0)

    LOADC(0);

    for (int c = 0; c < nch; c++) {
        if (c + 1 < nch) {
            LOADC(c + 1);
            asm volatile("cp.async.wait_group 1;");
        } else {
            asm volatile("cp.async.wait_group 0;");
        }
        __syncthreads();

        int s = c & 1;
        #pragma unroll
        for (int kk = 0; kk < 4; kk++) {
            uint32_t ah[2][4];
            #pragma unroll
            for (int mi = 0; mi < 2; mi++)
                ldsm4(ah[mi], aH[s] + aoff + mi * (16 * SP * 2) + kk * 32);
            #pragma unroll
            for (int np = 0; np < 4; np++) {
                uint32_t b[4];
                ldsm4(b, bS[s] + boff + np * (16 * SP * 2) + kk * 32);
                #pragma unroll
                for (int mi = 0; mi < 2; mi++) {
                    mma16816(acc[mi][2 * np],     ah[mi], b[0], b[1]);
                    mma16816(acc[mi][2 * np + 1], ah[mi], b[2], b[3]);
                }
            }
        }
        __syncthreads();
    }
#undef LOADC
}

#define EPI_IDX()                                                             \
    int lane = threadIdx.x & 31, wid = threadIdx.x >> 5;                      \
    int wm = wid & 3, wn = wid >> 2;                                          \
    int g4 = lane >> 2, tg = lane & 3;

#define ZERO_ACC(acc)                                                         \
    _Pragma("unroll")                                                         \
    for (int _a = 0; _a < 2; _a++)                                            \
        _Pragma("unroll")                                                     \
        for (int _b = 0; _b < 8; _b++)                                        \
            _Pragma("unroll")                                                 \
            for (int _c = 0; _c < 4; _c++) (acc)[_a][_b][_c] = 0.f;

// ---------------------------------------------------------------------------
// Fused QKV projection (single-pass fp16): z selects weight and destination.
// ---------------------------------------------------------------------------
__global__ __launch_bounds__(256, 2)
void proj_kernel(const hf* __restrict__ xh,
                 const hf* __restrict__ wq, const hf* __restrict__ wk,
                 const hf* __restrict__ wv,
                 hf* __restrict__ qh, hf* __restrict__ kh, hf* __restrict__ v)
{
    extern __shared__ char smem[];
    int rm = blockIdx.y * 128, cn = blockIdx.x * 128, z = blockIdx.z;
    const hf* B  = (z == 0) ? wq : (z == 1) ? wk : wv;
    hf* dst      = (z == 0) ? qh : (z == 1) ? kh : v;

    float acc[2][8][4];
    ZERO_ACC(acc);
    gemm_core(xh, B, CC, rm, cn, CC, smem, acc);

    EPI_IDX();
    #pragma unroll
    for (int mi = 0; mi < 2; mi++)
        #pragma unroll
        for (int ni = 0; ni < 8; ni++) {
            int r0 = rm + wm * 32 + mi * 16 + g4;
            int cb = cn + wn * 64 + ni * 8 + tg * 2;
            *(__half2*)(dst + (size_t)r0 * CC + cb) =
                __halves2half2(__float2half_rn(acc[mi][ni][0]),
                               __float2half_rn(acc[mi][ni][1]));
            *(__half2*)(dst + (size_t)(r0 + 8) * CC + cb) =
                __halves2half2(__float2half_rn(acc[mi][ni][2]),
                               __float2half_rn(acc[mi][ni][3]));
        }
}

// ---------------------------------------------------------------------------
// scores = scale * q @ k^T  — triangular tile launch, single-pass fp16
// ---------------------------------------------------------------------------
__global__ __launch_bounds__(256, 2)
void score_kernel(const hf* __restrict__ qh, const hf* __restrict__ kh,
                  float* __restrict__ w, float scale)
{
    extern __shared__ char smem[];
    int ti = blockIdx.x;                          // 0..135
    int i = (int)((sqrtf(8.f * ti + 1.f) - 1.f) * 0.5f);
    while ((i + 1) * (i + 2) / 2 <= ti) i++;
    while (i * (i + 1) / 2 > ti) i--;
    int j = ti - i * (i + 1) / 2;
    int rm = i * 128, cn = j * 128;

    int bz = blockIdx.z;
    qh += (size_t)bz * TT * CC;  kh += (size_t)bz * TT * CC;
    w  += (size_t)bz * TT * TT;

    float acc[2][8][4];
    ZERO_ACC(acc);
    gemm_core(qh, kh, CC, rm, cn, CC, smem, acc);

    EPI_IDX();
    #pragma unroll
    for (int mi = 0; mi < 2; mi++)
        #pragma unroll
        for (int ni = 0; ni < 8; ni++) {
            int r0 = rm + wm * 32 + mi * 16 + g4;
            int cb = cn + wn * 64 + ni * 8 + tg * 2;
            *(float2*)(w + (size_t)r0 * TT + cb) =
                make_float2(acc[mi][ni][0] * scale, acc[mi][ni][1] * scale);
            *(float2*)(w + (size_t)(r0 + 8) * TT + cb) =
                make_float2(acc[mi][ni][2] * scale, acc[mi][ni][3] * scale);
        }
}

// ---------------------------------------------------------------------------
// out = P @ V  — single-pass P-hi. vT is [C][T] K-major; k-loop truncated.
// ---------------------------------------------------------------------------
__global__ __launch_bounds__(256, 2)
void pv_kernel(const hf* __restrict__ ph, const hf* __restrict__ vt,
               float* __restrict__ out)
{
    extern __shared__ char smem[];
    int iy = gridDim.y - 1 - blockIdx.y;          // heavy tiles first
    int rm = iy * 128, cn = blockIdx.x * 128;
    int kmax = rm + 128;

    int bz = blockIdx.z;
    ph += (size_t)bz * TT * TT;
    vt += (size_t)bz * CC * TT;  out += (size_t)bz * TT * CC;

    float acc[2][8][4];
    ZERO_ACC(acc);
    gemm_core(ph, vt, TT, rm, cn, kmax, smem, acc);

    EPI_IDX();
    #pragma unroll
    for (int mi = 0; mi < 2; mi++)
        #pragma unroll
        for (int ni = 0; ni < 8; ni++) {
            int r0 = rm + wm * 32 + mi * 16 + g4;
            int cb = cn + wn * 64 + ni * 8 + tg * 2;
            *(float2*)(out + (size_t)r0 * CC + cb) =
                make_float2(acc[mi][ni][0], acc[mi][ni][1]);
            *(float2*)(out + (size_t)(r0 + 8) * CC + cb) =
                make_float2(acc[mi][ni][2], acc[mi][ni][3]);
        }
}

// ---------------------------------------------------------------------------
// input conversions (fp32 -> fp16, rounded)
// ---------------------------------------------------------------------------
__global__ __launch_bounds__(256)
void conv_h(const float* __restrict__ in, hf* __restrict__ h, int n)
{
    int i = blockIdx.x * 256 + threadIdx.x;
    if (i < n) h[i] = __float2half_rn(in[i]);
}
__global__ __launch_bounds__(256)
void conv3(const float* __restrict__ a, const float* __restrict__ b,
           const float* __restrict__ c, hf* __restrict__ oa,
           hf* __restrict__ ob, hf* __restrict__ oc, int n)
{
    int z = blockIdx.y;
    const float* in = (z == 0) ? a : (z == 1) ? b : c;
    hf* o = (z == 0) ? oa : (z == 1) ? ob : oc;
    int i = blockIdx.x * 256 + threadIdx.x;
    if (i < n) o[i] = __float2half_rn(in[i]);
}

// ---------------------------------------------------------------------------
// V [B,T,C] fp16 -> V^T [B,C,T] fp16 (K-major for the PV NT GEMM)
// ---------------------------------------------------------------------------
__global__ __launch_bounds__(256)
void tsplit_v(const hf* __restrict__ v, hf* __restrict__ oh)
{
    __shared__ float t[32][33];
    int b = blockIdx.z;
    const hf* vb = v + (size_t)b * TT * CC;
    hf* ohb = oh + (size_t)b * CC * TT;
    int c0 = blockIdx.x * 32, t0 = blockIdx.y * 32;
    int tx = threadIdx.x, ty = threadIdx.y;          // (32, 8)

    #pragma unroll
    for (int i = 0; i < 4; i++)
        t[ty + i * 8][tx] = __half2float(vb[(size_t)(t0 + ty + i * 8) * CC + c0 + tx]);
    __syncthreads();
    #pragma unroll
    for (int i = 0; i < 4; i++) {
        float f = t[tx][ty + i * 8];                 // = v[t0+tx][c0+ty+8i]
        ohb[(size_t)(c0 + ty + i * 8) * TT + t0 + tx] = __float2half_rn(f);
    }
}

// ---------------------------------------------------------------------------
// causal softmax over raw scores w (fp32) -> fp16 probs (hi only).
// exp recomputed in pass 3 so w is never written back.
// ---------------------------------------------------------------------------
__global__ __launch_bounds__(256)
void softmax_h(const float* __restrict__ w, hf* __restrict__ ph)
{
    int row = blockIdx.x;
    int b = row >> 11, t = row & 2047;
    const float* p = w  + ((size_t)b * TT + t) * TT;
    hf*          o = ph + ((size_t)b * TT + t) * TT;
    int n = t + 1;
    int tid = threadIdx.x;

    __shared__ float red[256];

    float m = -1e30f;
    for (int i = tid; i < n; i += 256) m = fmaxf(m, p[i]);
    red[tid] = m; __syncthreads();
    for (int s = 128; s > 0; s >>= 1) {
        if (tid < s) red[tid] = fmaxf(red[tid], red[tid + s]);
        __syncthreads();
    }
    m = red[0]; __syncthreads();

    float sum = 0.f;
    for (int i = tid; i < n; i += 256) sum += __expf(p[i] - m);
    red[tid] = sum; __syncthreads();
    for (int s = 128; s > 0; s >>= 1) {
        if (tid < s) red[tid] += red[tid + s];
        __syncthreads();
    }
    float inv = 1.f / red[0];

    for (int i = tid * 2; i < TT; i += 512) {
        float e0 = (i     < n) ? __expf(p[i]     - m) * inv : 0.f;
        float e1 = (i + 1 < n) ? __expf(p[i + 1] - m) * inv : 0.f;
        *(__half2*)(o + i) =
            __halves2half2(__float2half_rn(e0), __float2half_rn(e1));
    }
}

// ---------------------------------------------------------------------------
extern "C" void kernel_launch(void* const* d_in, const int* in_sizes, int n_in,
                              void* d_out, int out_size)
{
    const float* x  = (const float*)d_in[0];
    const float* Wk = (const float*)d_in[1];
    const float* Wq = (const float*)d_in[2];
    const float* Wv = (const float*)d_in[3];
    float* out = (float*)d_out;

    hf *xh, *wq, *wk, *wv, *qh, *kh, *v, *vt, *ph;
    float *w;
    cudaGetSymbolAddress((void**)&xh, g_xh);
    cudaGetSymbolAddress((void**)&wq, g_wq); cudaGetSymbolAddress((void**)&wk, g_wk);
    cudaGetSymbolAddress((void**)&wv, g_wv);
    cudaGetSymbolAddress((void**)&qh, g_qh); cudaGetSymbolAddress((void**)&kh, g_kh);
    cudaGetSymbolAddress((void**)&v, g_v);   cudaGetSymbolAddress((void**)&vt, g_vt);
    cudaGetSymbolAddress((void**)&w, g_w);
    cudaGetSymbolAddress((void**)&ph, g_ph);

    cudaFuncSetAttribute(proj_kernel,  cudaFuncAttributeMaxDynamicSharedMemorySize, PSM);
    cudaFuncSetAttribute(score_kernel, cudaFuncAttributeMaxDynamicSharedMemorySize, PSM);
    cudaFuncSetAttribute(pv_kernel,    cudaFuncAttributeMaxDynamicSharedMemorySize, PSM);

    const float scale = 1.0f / 32.0f;   // C^-0.5

    // 1) input conversions (all fp16 hi)
    conv_h<<<(MT * CC + 255) / 256, 256>>>(x, xh, MT * CC);
    conv3<<<dim3((CC * CC + 255) / 256, 3), 256>>>(Wq, Wk, Wv, wq, wk, wv, CC * CC);

    // 2) fused QKV projection, single-pass fp16
    proj_kernel<<<dim3(CC / 128, MT / 128, 3), 256, PSM>>>(
        xh, wq, wk, wv, qh, kh, v);

    // 3) V -> V^T fp16
    tsplit_v<<<dim3(CC / 32, TT / 32, BB), dim3(32, 8)>>>(v, vt);

    // 4) scores (triangular tile set, single-pass)
    score_kernel<<<dim3(136, 1, BB), 256, PSM>>>(qh, kh, w, scale);

    // 5) softmax -> fp16 probs
    softmax_h<<<BB * TT, 256>>>(w, ph);

    // 6) out = P @ V (single-pass)
    pv_kernel<<<dim3(CC / 128, TT / 128, BB), 256, PSM>>>(ph, vt, out);
}

// round 8
// speedup vs baseline: 6.8436x; 1.0671x over previous
#include <cuda_runtime.h>
#include <cuda_fp16.h>
#include <cstdint>
#include <math.h>

#define BB 4
#define TT 2048
#define CC 1024
#define MT (BB*TT)            /* 8192 flattened token rows */

typedef __half hf;

// ---------------- scratch (__device__ globals; no allocs allowed) ----------
__device__ hf    g_xh[MT*CC];
__device__ hf    g_wq[CC*CC],  g_wk[CC*CC],  g_wv[CC*CC];
__device__ hf    g_qh[MT*CC];
__device__ hf    g_kh[MT*CC];
__device__ hf    g_v[MT*CC];
__device__ float g_w[(size_t)BB*TT*TT];
__device__ hf    g_ph[(size_t)BB*TT*TT];

// ---------------- helpers ---------------------------------------------------
__device__ __forceinline__ uint32_t smem_u32(const void* p) {
    uint32_t a;
    asm("{ .reg .u64 t; cvta.to.shared.u64 t, %1; cvt.u32.u64 %0, t; }"
        : "=r"(a) : "l"(p));
    return a;
}
__device__ __forceinline__ void cpa16(uint32_t d, const void* s) {
    asm volatile("cp.async.cg.shared.global [%0], [%1], 16;" :: "r"(d), "l"(s));
}
__device__ __forceinline__ void cp_commit() {
    asm volatile("cp.async.commit_group;");
}
__device__ __forceinline__ void ldsm4(uint32_t* r, uint32_t addr) {
    asm volatile("ldmatrix.sync.aligned.m8n8.x4.shared.b16 {%0,%1,%2,%3}, [%4];"
        : "=r"(r[0]), "=r"(r[1]), "=r"(r[2]), "=r"(r[3]) : "r"(addr));
}
__device__ __forceinline__ void ldsm4t(uint32_t* r, uint32_t addr) {
    asm volatile("ldmatrix.sync.aligned.m8n8.x4.trans.shared.b16 {%0,%1,%2,%3}, [%4];"
        : "=r"(r[0]), "=r"(r[1]), "=r"(r[2]), "=r"(r[3]) : "r"(addr));
}
__device__ __forceinline__ void mma16816(float* c, const uint32_t* a,
                                         uint32_t b0, uint32_t b1) {
    asm volatile("mma.sync.aligned.m16n8k16.row.col.f32.f16.f16.f32 "
        "{%0,%1,%2,%3}, {%4,%5,%6,%7}, {%8,%9}, {%0,%1,%2,%3};"
        : "+f"(c[0]), "+f"(c[1]), "+f"(c[2]), "+f"(c[3])
        : "r"(a[0]), "r"(a[1]), "r"(a[2]), "r"(a[3]), "r"(b0), "r"(b1));
}

// ---------------------------------------------------------------------------
// fp16 warp-MMA GEMM core (NT): acc += A . B^T, A:[M,K], B:[N,K] row-major.
// CTA tile 128x128, BK=64, 8 warps (4m x 2n, warp tile 32x64),
// 2-stage cp.async. Pitch-72 smem rows (conflict-free ldmatrix).
// ---------------------------------------------------------------------------
#define SP 72                      /* smem row pitch, elements */
#define TB (128 * SP * 2)          /* 18432 B per 128x64 tile buffer */
#define PSM (4 * TB)               /* {A,B} x 2 stages = 73728 B */

__device__ __forceinline__ void gemm_core(
    const hf* __restrict__ Ah, const hf* __restrict__ Bh,
    int K, int rm, int cn, int kmax, char* smem, float acc[2][8][4])
{
    uint32_t sb = smem_u32(smem);
    uint32_t aH[2] = { sb,          sb + TB };
    uint32_t bS[2] = { sb + 2*TB,   sb + 3*TB };

    int tid = threadIdx.x, lane = tid & 31, wid = tid >> 5;
    int wm = wid & 3, wn = wid >> 2;

    int l_row = tid >> 3;          // 0..31
    int l_c   = (tid & 7) * 8;     // element col 0..56 (16B chunks)

    uint32_t aoff = ((uint32_t)(wm * 32 + (lane & 15)) * SP + (lane >> 4) * 8) * 2u;
    uint32_t boff = ((uint32_t)(wn * 64 + ((lane >> 4) & 1) * 8 + (lane & 7)) * SP
                     + ((lane >> 3) & 1) * 8) * 2u;

    int nch = kmax >> 6;

#define LOADC(cc) do {                                                        \
    int _s = (cc) & 1; size_t _k0 = (size_t)(cc) * 64;                        \
    _Pragma("unroll")                                                         \
    for (int _i = 0; _i < 4; _i++) {                                          \
        int _r = l_row + 32 * _i;                                             \
        uint32_t _so = ((uint32_t)_r * SP + l_c) * 2u;                        \
        cpa16(aH[_s] + _so, Ah + (size_t)(rm + _r) * K + _k0 + l_c);          \
        cpa16(bS[_s] + _so, Bh + (size_t)(cn + _r) * K + _k0 + l_c);          \
    }                                                                         \
    cp_commit();                                                              \
} while (0)

    LOADC(0);

    for (int c = 0; c < nch; c++) {
        if (c + 1 < nch) {
            LOADC(c + 1);
            asm volatile("cp.async.wait_group 1;");
        } else {
            asm volatile("cp.async.wait_group 0;");
        }
        __syncthreads();

        int s = c & 1;
        #pragma unroll
        for (int kk = 0; kk < 4; kk++) {
            uint32_t ah[2][4];
            #pragma unroll
            for (int mi = 0; mi < 2; mi++)
                ldsm4(ah[mi], aH[s] + aoff + mi * (16 * SP * 2) + kk * 32);
            #pragma unroll
            for (int np = 0; np < 4; np++) {
                uint32_t b[4];
                ldsm4(b, bS[s] + boff + np * (16 * SP * 2) + kk * 32);
                #pragma unroll
                for (int mi = 0; mi < 2; mi++) {
                    mma16816(acc[mi][2 * np],     ah[mi], b[0], b[1]);
                    mma16816(acc[mi][2 * np + 1], ah[mi], b[2], b[3]);
                }
            }
        }
        __syncthreads();
    }
#undef LOADC
}

#define EPI_IDX()                                                             \
    int lane = threadIdx.x & 31, wid = threadIdx.x >> 5;                      \
    int wm = wid & 3, wn = wid >> 2;                                          \
    int g4 = lane >> 2, tg = lane & 3;

#define ZERO_ACC(acc)                                                         \
    _Pragma("unroll")                                                         \
    for (int _a = 0; _a < 2; _a++)                                            \
        _Pragma("unroll")                                                     \
        for (int _b = 0; _b < 8; _b++)                                        \
            _Pragma("unroll")                                                 \
            for (int _c = 0; _c < 4; _c++) (acc)[_a][_b][_c] = 0.f;

// ---------------------------------------------------------------------------
// Fused QKV projection (single-pass fp16): z selects weight and destination.
// ---------------------------------------------------------------------------
__global__ __launch_bounds__(256, 2)
void proj_kernel(const hf* __restrict__ xh,
                 const hf* __restrict__ wq, const hf* __restrict__ wk,
                 const hf* __restrict__ wv,
                 hf* __restrict__ qh, hf* __restrict__ kh, hf* __restrict__ v)
{
    extern __shared__ char smem[];
    int rm = blockIdx.y * 128, cn = blockIdx.x * 128, z = blockIdx.z;
    const hf* B  = (z == 0) ? wq : (z == 1) ? wk : wv;
    hf* dst      = (z == 0) ? qh : (z == 1) ? kh : v;

    float acc[2][8][4];
    ZERO_ACC(acc);
    gemm_core(xh, B, CC, rm, cn, CC, smem, acc);

    EPI_IDX();
    #pragma unroll
    for (int mi = 0; mi < 2; mi++)
        #pragma unroll
        for (int ni = 0; ni < 8; ni++) {
            int r0 = rm + wm * 32 + mi * 16 + g4;
            int cb = cn + wn * 64 + ni * 8 + tg * 2;
            *(__half2*)(dst + (size_t)r0 * CC + cb) =
                __halves2half2(__float2half_rn(acc[mi][ni][0]),
                               __float2half_rn(acc[mi][ni][1]));
            *(__half2*)(dst + (size_t)(r0 + 8) * CC + cb) =
                __halves2half2(__float2half_rn(acc[mi][ni][2]),
                               __float2half_rn(acc[mi][ni][3]));
        }
}

// ---------------------------------------------------------------------------
// scores = scale * q @ k^T  — triangular tile launch, single-pass fp16
// ---------------------------------------------------------------------------
__global__ __launch_bounds__(256, 2)
void score_kernel(const hf* __restrict__ qh, const hf* __restrict__ kh,
                  float* __restrict__ w, float scale)
{
    extern __shared__ char smem[];
    int ti = blockIdx.x;                          // 0..135
    int i = (int)((sqrtf(8.f * ti + 1.f) - 1.f) * 0.5f);
    while ((i + 1) * (i + 2) / 2 <= ti) i++;
    while (i * (i + 1) / 2 > ti) i--;
    int j = ti - i * (i + 1) / 2;
    int rm = i * 128, cn = j * 128;

    int bz = blockIdx.z;
    qh += (size_t)bz * TT * CC;  kh += (size_t)bz * TT * CC;
    w  += (size_t)bz * TT * TT;

    float acc[2][8][4];
    ZERO_ACC(acc);
    gemm_core(qh, kh, CC, rm, cn, CC, smem, acc);

    EPI_IDX();
    #pragma unroll
    for (int mi = 0; mi < 2; mi++)
        #pragma unroll
        for (int ni = 0; ni < 8; ni++) {
            int r0 = rm + wm * 32 + mi * 16 + g4;
            int cb = cn + wn * 64 + ni * 8 + tg * 2;
            *(float2*)(w + (size_t)r0 * TT + cb) =
                make_float2(acc[mi][ni][0] * scale, acc[mi][ni][1] * scale);
            *(float2*)(w + (size_t)(r0 + 8) * TT + cb) =
                make_float2(acc[mi][ni][2] * scale, acc[mi][ni][3] * scale);
        }
}

// ---------------------------------------------------------------------------
// out = P @ V  (NN): P [T,T] row-major, V [T,C] row-major consumed directly
// via ldmatrix.trans B fragments. k-loop truncated at the diagonal.
// B smem tile: 64 k-rows x 128 n-cols, pitch 136 elements (272 B rows).
// ---------------------------------------------------------------------------
#define BP 136                       /* pv B tile pitch, elements */
#define PVA TB                       /* A buffer: 128 x 64, pitch 72 */
#define PVB (64 * BP * 2)            /* 17408 B */
#define PVSM (2 * (PVA + PVB))       /* 71680 B */

__global__ __launch_bounds__(256, 2)
void pv_kernel(const hf* __restrict__ ph, const hf* __restrict__ v,
               float* __restrict__ out)
{
    extern __shared__ char smem[];
    int iy = gridDim.y - 1 - blockIdx.y;          // heavy tiles first
    int rm = iy * 128, cn = blockIdx.x * 128;
    int kmax = rm + 128;

    int bz = blockIdx.z;
    ph  += (size_t)bz * TT * TT;
    v   += (size_t)bz * TT * CC;  out += (size_t)bz * TT * CC;

    uint32_t sb = smem_u32(smem);
    uint32_t aH[2] = { sb,               sb + PVA };
    uint32_t bS[2] = { sb + 2*PVA,       sb + 2*PVA + PVB };

    int tid = threadIdx.x, lane = tid & 31, wid = tid >> 5;
    int wm = wid & 3, wn = wid >> 2;

    int la_row = tid >> 3;            // A loader: 0..31
    int la_c   = (tid & 7) * 8;
    int lb_row = tid >> 4;            // B loader: 0..15 (x4 iters)
    int lb_c   = (tid & 15) * 8;      // 0..120

    uint32_t aoff  = ((uint32_t)(wm * 32 + (lane & 15)) * SP + (lane >> 4) * 8) * 2u;
    // trans-B lane address: k-row = (lane&7) + 8*((lane>>3)&1), n-col base += 8*((lane>>4)&1)
    uint32_t bofft = ((uint32_t)((lane & 7) + ((lane >> 3) & 1) * 8) * BP
                      + (uint32_t)(wn * 64 + ((lane >> 4) & 1) * 8)) * 2u;

    float acc[2][8][4];
    ZERO_ACC(acc);

    int nch = kmax >> 6;

#define LOADPV(cc) do {                                                       \
    int _s = (cc) & 1; size_t _k0 = (size_t)(cc) * 64;                        \
    _Pragma("unroll")                                                         \
    for (int _i = 0; _i < 4; _i++) {                                          \
        int _r = la_row + 32 * _i;                                            \
        cpa16(aH[_s] + ((uint32_t)_r * SP + la_c) * 2u,                       \
              ph + (size_t)(rm + _r) * TT + _k0 + la_c);                      \
    }                                                                         \
    _Pragma("unroll")                                                         \
    for (int _i = 0; _i < 4; _i++) {                                          \
        int _r = lb_row + 16 * _i;                                            \
        cpa16(bS[_s] + ((uint32_t)_r * BP + lb_c) * 2u,                       \
              v + (size_t)(_k0 + _r) * CC + cn + lb_c);                       \
    }                                                                         \
    cp_commit();                                                              \
} while (0)

    LOADPV(0);

    for (int c = 0; c < nch; c++) {
        if (c + 1 < nch) {
            LOADPV(c + 1);
            asm volatile("cp.async.wait_group 1;");
        } else {
            asm volatile("cp.async.wait_group 0;");
        }
        __syncthreads();

        int s = c & 1;
        #pragma unroll
        for (int kk = 0; kk < 4; kk++) {
            uint32_t ah[2][4];
            #pragma unroll
            for (int mi = 0; mi < 2; mi++)
                ldsm4(ah[mi], aH[s] + aoff + mi * (16 * SP * 2) + kk * 32);
            #pragma unroll
            for (int np = 0; np < 4; np++) {
                uint32_t b[4];
                ldsm4t(b, bS[s] + bofft + ((uint32_t)kk * 16 * BP + np * 16) * 2u);
                #pragma unroll
                for (int mi = 0; mi < 2; mi++) {
                    mma16816(acc[mi][2 * np],     ah[mi], b[0], b[1]);
                    mma16816(acc[mi][2 * np + 1], ah[mi], b[2], b[3]);
                }
            }
        }
        __syncthreads();
    }
#undef LOADPV

    EPI_IDX2:;
    int g4 = lane >> 2, tg = lane & 3;
    #pragma unroll
    for (int mi = 0; mi < 2; mi++)
        #pragma unroll
        for (int ni = 0; ni < 8; ni++) {
            int r0 = rm + wm * 32 + mi * 16 + g4;
            int cb = cn + wn * 64 + ni * 8 + tg * 2;
            *(float2*)(out + (size_t)r0 * CC + cb) =
                make_float2(acc[mi][ni][0], acc[mi][ni][1]);
            *(float2*)(out + (size_t)(r0 + 8) * CC + cb) =
                make_float2(acc[mi][ni][2], acc[mi][ni][3]);
        }
}

// ---------------------------------------------------------------------------
// input conversions (fp32 -> fp16, rounded)
// ---------------------------------------------------------------------------
__global__ __launch_bounds__(256)
void conv_h(const float* __restrict__ in, hf* __restrict__ h, int n)
{
    int i = blockIdx.x * 256 + threadIdx.x;
    if (i < n) h[i] = __float2half_rn(in[i]);
}
__global__ __launch_bounds__(256)
void conv3(const float* __restrict__ a, const float* __restrict__ b,
           const float* __restrict__ c, hf* __restrict__ oa,
           hf* __restrict__ ob, hf* __restrict__ oc, int n)
{
    int z = blockIdx.y;
    const float* in = (z == 0) ? a : (z == 1) ? b : c;
    hf* o = (z == 0) ? oa : (z == 1) ? ob : oc;
    int i = blockIdx.x * 256 + threadIdx.x;
    if (i < n) o[i] = __float2half_rn(in[i]);
}

// ---------------------------------------------------------------------------
// causal softmax, single global read: row cached in 8 regs/thread.
// exp(-1e30 - m) underflows to 0 -> free zero-fill above the diagonal.
// ---------------------------------------------------------------------------
__global__ __launch_bounds__(256)
void softmax_h(const float* __restrict__ w, hf* __restrict__ ph)
{
    int row = blockIdx.x;
    int b = row >> 11, t = row & 2047;
    const float* p = w  + ((size_t)b * TT + t) * TT;
    hf*          o = ph + ((size_t)b * TT + t) * TT;
    int n = t + 1;
    int tid = threadIdx.x;

    __shared__ float red[8];
    int lane = tid & 31, wrp = tid >> 5;

    float r[8];
    #pragma unroll
    for (int j = 0; j < 8; j++) {
        int i = tid + 256 * j;
        r[j] = (i < n) ? p[i] : -1e30f;
    }

    float m = r[0];
    #pragma unroll
    for (int j = 1; j < 8; j++) m = fmaxf(m, r[j]);
    #pragma unroll
    for (int s = 16; s > 0; s >>= 1)
        m = fmaxf(m, __shfl_xor_sync(0xffffffffu, m, s));
    if (lane == 0) red[wrp] = m;
    __syncthreads();
    m = red[0];
    #pragma unroll
    for (int j = 1; j < 8; j++) m = fmaxf(m, red[j]);
    __syncthreads();

    float sum = 0.f;
    #pragma unroll
    for (int j = 0; j < 8; j++) {
        float e = __expf(r[j] - m);
        r[j] = e;
        sum += e;
    }
    #pragma unroll
    for (int s = 16; s > 0; s >>= 1)
        sum += __shfl_xor_sync(0xffffffffu, sum, s);
    if (lane == 0) red[wrp] = sum;
    __syncthreads();
    sum = red[0];
    #pragma unroll
    for (int j = 1; j < 8; j++) sum += red[j];
    float inv = 1.f / sum;

    #pragma unroll
    for (int j = 0; j < 8; j++)
        o[tid + 256 * j] = __float2half_rn(r[j] * inv);
}

// ---------------------------------------------------------------------------
extern "C" void kernel_launch(void* const* d_in, const int* in_sizes, int n_in,
                              void* d_out, int out_size)
{
    const float* x  = (const float*)d_in[0];
    const float* Wk = (const float*)d_in[1];
    const float* Wq = (const float*)d_in[2];
    const float* Wv = (const float*)d_in[3];
    float* out = (float*)d_out;

    hf *xh, *wq, *wk, *wv, *qh, *kh, *v, *ph;
    float *w;
    cudaGetSymbolAddress((void**)&xh, g_xh);
    cudaGetSymbolAddress((void**)&wq, g_wq); cudaGetSymbolAddress((void**)&wk, g_wk);
    cudaGetSymbolAddress((void**)&wv, g_wv);
    cudaGetSymbolAddress((void**)&qh, g_qh); cudaGetSymbolAddress((void**)&kh, g_kh);
    cudaGetSymbolAddress((void**)&v, g_v);
    cudaGetSymbolAddress((void**)&w, g_w);
    cudaGetSymbolAddress((void**)&ph, g_ph);

    cudaFuncSetAttribute(proj_kernel,  cudaFuncAttributeMaxDynamicSharedMemorySize, PSM);
    cudaFuncSetAttribute(score_kernel, cudaFuncAttributeMaxDynamicSharedMemorySize, PSM);
    cudaFuncSetAttribute(pv_kernel,    cudaFuncAttributeMaxDynamicSharedMemorySize, PVSM);

    const float scale = 1.0f / 32.0f;   // C^-0.5

    // 1) input conversions (all fp16 hi)
    conv_h<<<(MT * CC + 255) / 256, 256>>>(x, xh, MT * CC);
    conv3<<<dim3((CC * CC + 255) / 256, 3), 256>>>(Wq, Wk, Wv, wq, wk, wv, CC * CC);

    // 2) fused QKV projection, single-pass fp16
    proj_kernel<<<dim3(CC / 128, MT / 128, 3), 256, PSM>>>(
        xh, wq, wk, wv, qh, kh, v);

    // 3) scores (triangular tile set, single-pass)
    score_kernel<<<dim3(136, 1, BB), 256, PSM>>>(qh, kh, w, scale);

    // 4) softmax -> fp16 probs (single read)
    softmax_h<<<BB * TT, 256>>>(w, ph);

    // 5) out = P @ V (direct V via trans-ldmatrix)
    pv_kernel<<<dim3(CC / 128, TT / 128, BB), 256, PVSM>>>(ph, v, out);
}